// round 1
// baseline (speedup 1.0000x reference)
#include <cuda_runtime.h>
#include <math.h>

#define BB   2
#define SQL  2048
#define SKL  2048
#define DM   1024
#define NH   16
#define DH   64
#define BH   (BB*NH)

// Scratch (allocation-free rule: __device__ globals)
__device__ float g_Qt[BH * DH * SQL];   // [bh][d][q]   (transposed)
__device__ float g_Kt[BH * DH * SKL];   // [bh][d][k]   (transposed)
__device__ float g_V [BH * SKL * DH];   // [bh][k][d]
__device__ float g_ctx[BB * SQL * DM];  // [b][s][h*64+d]

// ---------------------------------------------------------------------------
// Generic tiled GEMM: C = X @ W + bias, X:[4096,1024], W:[1024,1024]
// mode 0: write transposed head layout [bh][d][s]  (for Q, K)
// mode 1: write head layout [bh][s][d]             (for V)
// mode 2: write flat [row][col]                    (for output proj)
// Tiles: BM=BN=64, BK=16; 256 threads; 4x4 per-thread microtile; reg prefetch.
// ---------------------------------------------------------------------------
__global__ __launch_bounds__(256)
void gemm_kernel(const float* __restrict__ X, const float* __restrict__ W,
                 const float* __restrict__ bias, float* __restrict__ out, int mode)
{
    __shared__ float As[64 * 16];
    __shared__ float Bs[16 * 64];

    const int t  = threadIdx.x;
    const int tx = t % 16;
    const int ty = t / 16;
    const int rowBase = blockIdx.y * 64;
    const int colBase = blockIdx.x * 64;

    const int arow = t / 4;          // 0..63
    const int ac4  = (t % 4) * 4;    // 0,4,8,12
    const int brow = t / 16;         // 0..15
    const int bc4  = (t % 16) * 4;   // 0..60

    const float* Aptr = X + (size_t)(rowBase + arow) * DM + ac4;
    const float* Bptr = W + (size_t)brow * DM + colBase + bc4;

    float4 aReg = *(const float4*)Aptr;
    float4 bReg = *(const float4*)Bptr;

    float acc[4][4];
#pragma unroll
    for (int i = 0; i < 4; i++)
#pragma unroll
        for (int j = 0; j < 4; j++) acc[i][j] = 0.0f;

    for (int k0 = 0; k0 < DM; k0 += 16) {
        *(float4*)&As[arow * 16 + ac4] = aReg;
        *(float4*)&Bs[brow * 64 + bc4] = bReg;
        __syncthreads();

        if (k0 + 16 < DM) {
            aReg = *(const float4*)(Aptr + (k0 + 16));
            bReg = *(const float4*)(Bptr + (size_t)(k0 + 16) * DM);
        }

#pragma unroll
        for (int kk = 0; kk < 16; kk++) {
            float a[4];
#pragma unroll
            for (int i = 0; i < 4; i++) a[i] = As[(ty * 4 + i) * 16 + kk];
            float4 b4 = *(const float4*)&Bs[kk * 64 + tx * 4];
            float b[4] = {b4.x, b4.y, b4.z, b4.w};
#pragma unroll
            for (int i = 0; i < 4; i++)
#pragma unroll
                for (int j = 0; j < 4; j++) acc[i][j] += a[i] * b[j];
        }
        __syncthreads();
    }

    // Epilogue
    const int col0 = colBase + tx * 4;
    float bb[4];
#pragma unroll
    for (int j = 0; j < 4; j++) bb[j] = bias[col0 + j];

#pragma unroll
    for (int i = 0; i < 4; i++) {
        const int row = rowBase + ty * 4 + i;
        if (mode == 2) {
            float4 v = make_float4(acc[i][0] + bb[0], acc[i][1] + bb[1],
                                   acc[i][2] + bb[2], acc[i][3] + bb[3]);
            *(float4*)&out[(size_t)row * DM + col0] = v;
        } else {
            const int b = row / SQL;
            const int s = row % SQL;
#pragma unroll
            for (int j = 0; j < 4; j++) {
                const int col = col0 + j;
                const int h = col / DH;
                const int d = col % DH;
                const float v = acc[i][j] + bb[j];
                if (mode == 0) {
                    // transposed: [bh][d][s]
                    out[((size_t)(b * NH + h) * DH + d) * SQL + s] = v;
                } else {
                    // [bh][s][d]
                    out[((size_t)(b * NH + h) * SQL + s) * DH + d] = v;
                }
            }
        }
    }
}

// ---------------------------------------------------------------------------
// Flash attention (fp32, online softmax).
// Block: 256 threads handles 64 queries of one (b,h). K-tiles of 64.
// smem (dynamic, 64 KB): Qs[d][q], Ks[d][k], Vs[k][d], Ps[q][k]  (all 64x64)
// Per-thread: 4x4 microtiles for S and O. Row reductions via shfl (width 16).
// ---------------------------------------------------------------------------
__global__ __launch_bounds__(256)
void attn_kernel(const float* __restrict__ Qt, const float* __restrict__ Kt,
                 const float* __restrict__ V, float* __restrict__ ctx)
{
    extern __shared__ float sm[];
    float* Qs = sm;                 // [d][q]
    float* Ks = sm + 64 * 64;       // [d][k]
    float* Vs = sm + 2 * 64 * 64;   // [k][d]
    float* Ps = sm + 3 * 64 * 64;   // [q][k]

    const int bh = blockIdx.y;      // 0..31
    const int q0 = blockIdx.x * 64;
    const int t  = threadIdx.x;
    const int tx = t % 16;
    const int ty = t / 16;
    const float scale = 0.125f;     // 1/sqrt(64)

    // Load Q tile (fold in softmax scale). Coalesced over q.
    {
        const int q  = t % 64;
        const int d0 = t / 64;
        const size_t base = (size_t)bh * DH * SQL;
#pragma unroll
        for (int i = 0; i < 16; i++) {
            const int d = d0 + i * 4;
            Qs[d * 64 + q] = Qt[base + (size_t)d * SQL + q0 + q] * scale;
        }
    }

    float o[4][4];
    float m[4], l[4];
#pragma unroll
    for (int i = 0; i < 4; i++) {
        m[i] = -INFINITY; l[i] = 0.0f;
#pragma unroll
        for (int j = 0; j < 4; j++) o[i][j] = 0.0f;
    }

    for (int k0 = 0; k0 < SKL; k0 += 64) {
        __syncthreads();   // protect Ks/Vs/Ps reuse from previous iteration

        // Load K tile [d][k] (coalesced over k) and V tile [k][d] (coalesced over d)
        {
            const int k  = t % 64;
            const int d0 = t / 64;
            const size_t kbase = (size_t)bh * DH * SKL;
#pragma unroll
            for (int i = 0; i < 16; i++) {
                const int d = d0 + i * 4;
                Ks[d * 64 + k] = Kt[kbase + (size_t)d * SKL + k0 + k];
            }
            const int d  = t % 64;
            const int kb = t / 64;
            const size_t vbase = (size_t)bh * SKL * DH;
#pragma unroll
            for (int i = 0; i < 16; i++) {
                const int kk = kb + i * 4;
                Vs[kk * 64 + d] = V[vbase + (size_t)(k0 + kk) * DH + d];
            }
        }
        __syncthreads();

        // S = (Q*scale) @ K^T   (4x4 per thread)
        float s[4][4];
#pragma unroll
        for (int i = 0; i < 4; i++)
#pragma unroll
            for (int j = 0; j < 4; j++) s[i][j] = 0.0f;

#pragma unroll 4
        for (int d = 0; d < 64; d++) {
            float4 qv = *(const float4*)&Qs[d * 64 + ty * 4];
            float4 kv = *(const float4*)&Ks[d * 64 + tx * 4];
            float qa[4] = {qv.x, qv.y, qv.z, qv.w};
            float ka[4] = {kv.x, kv.y, kv.z, kv.w};
#pragma unroll
            for (int i = 0; i < 4; i++)
#pragma unroll
                for (int j = 0; j < 4; j++) s[i][j] += qa[i] * ka[j];
        }

        // Online softmax update per query row
#pragma unroll
        for (int i = 0; i < 4; i++) {
            float tm = fmaxf(fmaxf(s[i][0], s[i][1]), fmaxf(s[i][2], s[i][3]));
#pragma unroll
            for (int off = 1; off < 16; off <<= 1)
                tm = fmaxf(tm, __shfl_xor_sync(0xffffffffu, tm, off, 16));
            const float mnew  = fmaxf(m[i], tm);
            const float alpha = __expf(m[i] - mnew);
            float psum = 0.0f;
#pragma unroll
            for (int j = 0; j < 4; j++) {
                const float p = __expf(s[i][j] - mnew);
                s[i][j] = p;
                psum += p;
            }
#pragma unroll
            for (int off = 1; off < 16; off <<= 1)
                psum += __shfl_xor_sync(0xffffffffu, psum, off, 16);
            l[i] = l[i] * alpha + psum;
            m[i] = mnew;
#pragma unroll
            for (int j = 0; j < 4; j++) o[i][j] *= alpha;
            *(float4*)&Ps[(ty * 4 + i) * 64 + tx * 4] =
                make_float4(s[i][0], s[i][1], s[i][2], s[i][3]);
        }
        __syncthreads();

        // O += P @ V
#pragma unroll 4
        for (int j = 0; j < 64; j++) {
            float p[4];
#pragma unroll
            for (int i = 0; i < 4; i++) p[i] = Ps[(ty * 4 + i) * 64 + j];
            float4 vv = *(const float4*)&Vs[j * 64 + tx * 4];
            float va[4] = {vv.x, vv.y, vv.z, vv.w};
#pragma unroll
            for (int i = 0; i < 4; i++)
#pragma unroll
                for (int c = 0; c < 4; c++) o[i][c] += p[i] * va[c];
        }
    }

    // Epilogue: normalize and write ctx[b][s][h*64+d]
    const int b = bh / NH;
    const int h = bh % NH;
#pragma unroll
    for (int i = 0; i < 4; i++) {
        const float inv = 1.0f / l[i];
        const int q = q0 + ty * 4 + i;
        float4 r = make_float4(o[i][0] * inv, o[i][1] * inv,
                               o[i][2] * inv, o[i][3] * inv);
        *(float4*)&g_ctx[((size_t)(b * SQL + q)) * DM + h * DH + tx * 4] = r;
    }
    (void)ctx;
}

// ---------------------------------------------------------------------------
extern "C" void kernel_launch(void* const* d_in, const int* in_sizes, int n_in,
                              void* d_out, int out_size)
{
    const float* x1 = (const float*)d_in[0];
    const float* x2 = (const float*)d_in[1];
    const float* Wq = (const float*)d_in[2];
    const float* bq = (const float*)d_in[3];
    const float* Wk = (const float*)d_in[4];
    const float* bk = (const float*)d_in[5];
    const float* Wv = (const float*)d_in[6];
    const float* bv = (const float*)d_in[7];
    const float* Wo = (const float*)d_in[8];
    const float* bo = (const float*)d_in[9];
    float* out = (float*)d_out;

    float *Qt, *Kt, *Vb, *ctx;
    cudaGetSymbolAddress((void**)&Qt,  g_Qt);
    cudaGetSymbolAddress((void**)&Kt,  g_Kt);
    cudaGetSymbolAddress((void**)&Vb,  g_V);
    cudaGetSymbolAddress((void**)&ctx, g_ctx);

    cudaFuncSetAttribute(attn_kernel,
                         cudaFuncAttributeMaxDynamicSharedMemorySize, 64 * 1024);

    dim3 ggrid(DM / 64, (BB * SQL) / 64);      // (16, 64)
    gemm_kernel<<<ggrid, 256>>>(x1, Wq, bq, Qt, 0);   // Q transposed
    gemm_kernel<<<ggrid, 256>>>(x2, Wk, bk, Kt, 0);   // K transposed
    gemm_kernel<<<ggrid, 256>>>(x2, Wv, bv, Vb, 1);   // V

    dim3 agrid(SQL / 64, BH);                  // (32, 32)
    attn_kernel<<<agrid, 256, 64 * 1024>>>(Qt, Kt, Vb, ctx);

    gemm_kernel<<<ggrid, 256>>>(ctx, Wo, bo, out, 2); // output projection
}

// round 3
// speedup vs baseline: 2.3046x; 2.3046x over previous
#include <cuda_runtime.h>
#include <cuda_bf16.h>
#include <math.h>
#include <stdint.h>

#define BB   2
#define SQL  2048
#define DM   1024
#define NH   16
#define DH   64
#define BH   32
#define ROWS 4096

typedef __nv_bfloat16 bf16;

// ---------------- scratch (__device__ globals) -----------------------------
__device__ bf16 g_Qh[BH * SQL * DH];
__device__ bf16 g_Ql[BH * SQL * DH];
__device__ bf16 g_Kh[BH * SQL * DH];
__device__ bf16 g_Kl[BH * SQL * DH];
__device__ bf16 g_Vh[BH * SQL * DH];
__device__ bf16 g_Vl[BH * SQL * DH];
__device__ bf16 g_Ah[ROWS * DM];
__device__ bf16 g_Al[ROWS * DM];
__device__ bf16 g_Wh[DM * DM];   // W^T [n][k]
__device__ bf16 g_Wl[DM * DM];

// ---------------- helpers --------------------------------------------------
__device__ __forceinline__ uint32_t smem_to_u32(const void* p) {
    uint32_t a;
    asm("{ .reg .u64 t; cvta.to.shared.u64 t, %1; cvt.u32.u64 %0, t; }"
        : "=r"(a) : "l"(p));
    return a;
}
__device__ __forceinline__ void ldsm4(uint32_t* r, uint32_t a) {
    asm volatile("ldmatrix.sync.aligned.m8n8.x4.shared.b16 {%0,%1,%2,%3}, [%4];"
        : "=r"(r[0]), "=r"(r[1]), "=r"(r[2]), "=r"(r[3]) : "r"(a));
}
__device__ __forceinline__ void ldsm4t(uint32_t* r, uint32_t a) {
    asm volatile("ldmatrix.sync.aligned.m8n8.x4.trans.shared.b16 {%0,%1,%2,%3}, [%4];"
        : "=r"(r[0]), "=r"(r[1]), "=r"(r[2]), "=r"(r[3]) : "r"(a));
}
__device__ __forceinline__ void mma16816(float* c, const uint32_t* a, const uint32_t* b) {
    asm volatile("mma.sync.aligned.m16n8k16.row.col.f32.bf16.bf16.f32 "
        "{%0,%1,%2,%3}, {%4,%5,%6,%7}, {%8,%9}, {%0,%1,%2,%3};"
        : "+f"(c[0]), "+f"(c[1]), "+f"(c[2]), "+f"(c[3])
        : "r"(a[0]), "r"(a[1]), "r"(a[2]), "r"(a[3]), "r"(b[0]), "r"(b[1]));
}
__device__ __forceinline__ void split2(float v0, float v1, uint32_t& hi2, uint32_t& lo2) {
    __nv_bfloat16 b0 = __float2bfloat16_rn(v0), b1 = __float2bfloat16_rn(v1);
    union { __nv_bfloat162 v; uint32_t u; } p;
    p.v.x = b0; p.v.y = b1; hi2 = p.u;
    p.v.x = __float2bfloat16_rn(v0 - __bfloat162float(b0));
    p.v.y = __float2bfloat16_rn(v1 - __bfloat162float(b1));
    lo2 = p.u;
}

// ---------------- conversion kernels ---------------------------------------
__global__ __launch_bounds__(256)
void convA_kernel(const float* __restrict__ x, bf16* __restrict__ hi,
                  bf16* __restrict__ lo)
{
    int i = blockIdx.x * 256 + threadIdx.x;       // over ROWS*DM/4 float4s
    float4 v = ((const float4*)x)[i];
    uint32_t h0, l0, h1, l1;
    split2(v.x, v.y, h0, l0);
    split2(v.z, v.w, h1, l1);
    ((uint32_t*)hi)[2 * i] = h0; ((uint32_t*)hi)[2 * i + 1] = h1;
    ((uint32_t*)lo)[2 * i] = l0; ((uint32_t*)lo)[2 * i + 1] = l1;
}

// transpose + split: W[k][n] -> Wt hi/lo [n][k]
__global__ __launch_bounds__(1024)
void convW_kernel(const float* __restrict__ W, bf16* __restrict__ hi,
                  bf16* __restrict__ lo)
{
    __shared__ float tile[32][33];
    int tx = threadIdx.x, ty = threadIdx.y;
    int k = blockIdx.y * 32 + ty;
    int n = blockIdx.x * 32 + tx;
    tile[ty][tx] = W[(size_t)k * DM + n];
    __syncthreads();
    int nn = blockIdx.x * 32 + ty;
    int kk = blockIdx.y * 32 + tx;
    float v = tile[tx][ty];
    __nv_bfloat16 h = __float2bfloat16_rn(v);
    hi[(size_t)nn * DM + kk] = h;
    lo[(size_t)nn * DM + kk] = __float2bfloat16_rn(v - __bfloat162float(h));
}

// ---------------- split-bf16 GEMM via mma.sync -----------------------------
// C[m][n] = sum_k (Ah+Al)[m][k] * (Bh+Bl)[n][k]; then (C + bias) * scale.
// outF != 0 : flat fp32 [m][DM].  else: split bf16 [bh][s][64] to outH/outL.
__global__ __launch_bounds__(256, 1)
void gemm_mma(const bf16* __restrict__ Ah, const bf16* __restrict__ Al,
              const bf16* __restrict__ Bh, const bf16* __restrict__ Bl,
              const float* __restrict__ bias,
              bf16* __restrict__ outH, bf16* __restrict__ outL,
              float* __restrict__ outF, float scale)
{
    __shared__ __align__(16) char sm_[40960];   // 4 tiles of 128 rows * 80B
    char* sAh = sm_;
    char* sBh = sm_ + 20480;
    const uint32_t sb = smem_to_u32(sm_);
    const int t = threadIdx.x, L = t & 31, wid = t >> 5;
    const int wm = wid >> 2, wn = wid & 3;
    const int m0 = blockIdx.y * 128, n0 = blockIdx.x * 128;

    float acc[4][4][4];
#pragma unroll
    for (int a = 0; a < 4; a++)
#pragma unroll
        for (int b = 0; b < 4; b++)
#pragma unroll
            for (int c = 0; c < 4; c++) acc[a][b][c] = 0.0f;

    const int r0 = t >> 2, c0 = t & 3;           // copy: row, 16B-chunk
    const int a_row_off = ((L >> 3) & 1) * 8 + (L & 7);
    const int a_ch = (L >> 4);
    const int b_row_off = ((L >> 4) & 1) * 8 + (L & 7);
    const int b_ch = ((L >> 3) & 1);

    for (int k0 = 0; k0 < DM; k0 += 32) {
        __syncthreads();
        {
            const size_t ga = (size_t)(m0 + r0) * DM + k0 + c0 * 8;
            const size_t gb = (size_t)(n0 + r0) * DM + k0 + c0 * 8;
            const int so = r0 * 80 + c0 * 16;
            *(uint4*)(sAh + so)         = *(const uint4*)(Ah + ga);
            *(uint4*)(sAh + 10240 + so) = *(const uint4*)(Al + ga);
            *(uint4*)(sBh + so)         = *(const uint4*)(Bh + gb);
            *(uint4*)(sBh + 10240 + so) = *(const uint4*)(Bl + gb);
            const int so2 = so + 64 * 80;
            *(uint4*)(sAh + so2)         = *(const uint4*)(Ah + ga + (size_t)64 * DM);
            *(uint4*)(sAh + 10240 + so2) = *(const uint4*)(Al + ga + (size_t)64 * DM);
            *(uint4*)(sBh + so2)         = *(const uint4*)(Bh + gb + (size_t)64 * DM);
            *(uint4*)(sBh + 10240 + so2) = *(const uint4*)(Bl + gb + (size_t)64 * DM);
        }
        __syncthreads();
#pragma unroll
        for (int ks = 0; ks < 2; ks++) {
            uint32_t aH[4][4], aL[4][4], bHf[2][4], bLf[2][4];
            const int ach = (2 * ks + a_ch) * 16;
#pragma unroll
            for (int mt = 0; mt < 4; mt++) {
                const uint32_t ad = sb + (wm * 64 + mt * 16 + a_row_off) * 80 + ach;
                ldsm4(aH[mt], ad);
                ldsm4(aL[mt], ad + 10240);
            }
            const int bch = (2 * ks + b_ch) * 16;
#pragma unroll
            for (int np = 0; np < 2; np++) {
                const uint32_t bd = sb + 20480 + (wn * 32 + np * 16 + b_row_off) * 80 + bch;
                ldsm4(bHf[np], bd);
                ldsm4(bLf[np], bd + 10240);
            }
#pragma unroll
            for (int mt = 0; mt < 4; mt++)
#pragma unroll
                for (int nt = 0; nt < 4; nt++) {
                    const uint32_t* bh_ = &bHf[nt >> 1][(nt & 1) * 2];
                    const uint32_t* bl_ = &bLf[nt >> 1][(nt & 1) * 2];
                    mma16816(acc[mt][nt], aH[mt], bh_);
                    mma16816(acc[mt][nt], aH[mt], bl_);
                    mma16816(acc[mt][nt], aL[mt], bh_);
                }
        }
    }

    // epilogue
    const int g = L >> 2, tg = L & 3;
#pragma unroll
    for (int mt = 0; mt < 4; mt++) {
#pragma unroll
        for (int nt = 0; nt < 4; nt++) {
            const int mrow = m0 + wm * 64 + mt * 16 + g;
            const int ncol = n0 + wn * 32 + nt * 8 + 2 * tg;
            const float b0v = bias[ncol], b1v = bias[ncol + 1];
            const float v00 = (acc[mt][nt][0] + b0v) * scale;
            const float v01 = (acc[mt][nt][1] + b1v) * scale;
            const float v10 = (acc[mt][nt][2] + b0v) * scale;
            const float v11 = (acc[mt][nt][3] + b1v) * scale;
            if (outF) {
                *(float2*)(outF + (size_t)mrow * DM + ncol) = make_float2(v00, v01);
                *(float2*)(outF + (size_t)(mrow + 8) * DM + ncol) = make_float2(v10, v11);
            } else {
                const int b_ = mrow >> 11, s_ = mrow & 2047;
                const int h_ = ncol >> 6, d_ = ncol & 63;
                const size_t oi = ((size_t)(b_ * NH + h_) * SQL + s_) * DH + d_;
                uint32_t h2, l2;
                split2(v00, v01, h2, l2);
                *(uint32_t*)(outH + oi) = h2;
                *(uint32_t*)(outL + oi) = l2;
                split2(v10, v11, h2, l2);
                *(uint32_t*)(outH + oi + 8 * DH) = h2;
                *(uint32_t*)(outL + oi + 8 * DH) = l2;
            }
        }
    }
}

// ---------------- flash attention via mma.sync (split-bf16) ----------------
// Grid: (SQL/128, BH). 256 threads = 8 warps; warp w owns q-rows w*16..+15.
// smem: Qh,Ql,Kh,Kl,Vh,Vl tiles 128x64 bf16, SW128 swizzled. 96KB.
#define SM_QH 0
#define SM_QL 16384
#define SM_KH 32768
#define SM_KL 49152
#define SM_VH 65536
#define SM_VL 81920
__global__ __launch_bounds__(256, 1)
void attn_mma(const bf16* __restrict__ Qh, const bf16* __restrict__ Ql,
              const bf16* __restrict__ Kh, const bf16* __restrict__ Kl,
              const bf16* __restrict__ Vh, const bf16* __restrict__ Vl,
              bf16* __restrict__ Ch, bf16* __restrict__ Cl)
{
    extern __shared__ char sm_[];
    const uint32_t sb = smem_to_u32(sm_);
    const int t = threadIdx.x, L = t & 31, wid = t >> 5;
    const int bh = blockIdx.y, q0 = blockIdx.x * 128;
    const int g = L >> 2, tg = L & 3;

    // load Q tiles once (hi+lo), SW128 swizzled
    {
        const size_t qgb = ((size_t)bh * SQL + q0) * DH;
#pragma unroll
        for (int i = 0; i < 4; i++) {
            const int u = t + i * 256, r = u >> 3, c = u & 7;
            const int so = r * 128 + ((c ^ (r & 7)) << 4);
            const size_t gi = qgb + r * 64 + c * 8;
            *(uint4*)(sm_ + SM_QH + so) = *(const uint4*)(Qh + gi);
            *(uint4*)(sm_ + SM_QL + so) = *(const uint4*)(Ql + gi);
        }
    }

    float oacc[8][4];
#pragma unroll
    for (int a = 0; a < 8; a++)
#pragma unroll
        for (int b = 0; b < 4; b++) oacc[a][b] = 0.0f;
    float m0r = -1e30f, m1r = -1e30f, l0r = 0.0f, l1r = 0.0f;

    const int a_row = wid * 16 + ((L >> 3) & 1) * 8 + (L & 7);
    const int a_cb  = (L >> 4);
    const int k_row_off = ((L >> 4) & 1) * 8 + (L & 7);
    const int k_cb  = ((L >> 3) & 1);
    const int v_row_off = ((L >> 3) & 1) * 8 + (L & 7);
    const int v_cb  = (L >> 4);
    const int sw    = L & 7;   // row&7 for all ldmatrix rows

    for (int kb = 0; kb < 16; kb++) {
        __syncthreads();
        {
            const size_t kgb = ((size_t)bh * SQL + kb * 128) * DH;
#pragma unroll
            for (int i = 0; i < 4; i++) {
                const int u = t + i * 256, r = u >> 3, c = u & 7;
                const int so = r * 128 + ((c ^ (r & 7)) << 4);
                const size_t gi = kgb + r * 64 + c * 8;
                *(uint4*)(sm_ + SM_KH + so) = *(const uint4*)(Kh + gi);
                *(uint4*)(sm_ + SM_KL + so) = *(const uint4*)(Kl + gi);
                *(uint4*)(sm_ + SM_VH + so) = *(const uint4*)(Vh + gi);
                *(uint4*)(sm_ + SM_VL + so) = *(const uint4*)(Vl + gi);
            }
        }
        __syncthreads();

        // ---- S = Q @ K^T (128 cols), fp32 accum ----
        float sacc[16][4];
#pragma unroll
        for (int j = 0; j < 16; j++)
#pragma unroll
            for (int c = 0; c < 4; c++) sacc[j][c] = 0.0f;

#pragma unroll
        for (int ks = 0; ks < 4; ks++) {
            uint32_t qh4[4], ql4[4];
            const uint32_t qa = sb + SM_QH + a_row * 128
                              + (((2 * ks + a_cb) ^ sw) << 4);
            ldsm4(qh4, qa);
            ldsm4(ql4, qa + 16384);
#pragma unroll
            for (int jp = 0; jp < 8; jp++) {
                uint32_t kh4[4], kl4[4];
                const int krow = jp * 16 + k_row_off;
                const uint32_t ka = sb + SM_KH + krow * 128
                                  + (((2 * ks + k_cb) ^ sw) << 4);
                ldsm4(kh4, ka);
                ldsm4(kl4, ka + 16384);
                mma16816(sacc[2 * jp],     qh4, &kh4[0]);
                mma16816(sacc[2 * jp],     qh4, &kl4[0]);
                mma16816(sacc[2 * jp],     ql4, &kh4[0]);
                mma16816(sacc[2 * jp + 1], qh4, &kh4[2]);
                mma16816(sacc[2 * jp + 1], qh4, &kl4[2]);
                mma16816(sacc[2 * jp + 1], ql4, &kh4[2]);
            }
        }

        // ---- online softmax ----
        float rx0 = -1e30f, rx1 = -1e30f;
#pragma unroll
        for (int j = 0; j < 16; j++) {
            rx0 = fmaxf(rx0, fmaxf(sacc[j][0], sacc[j][1]));
            rx1 = fmaxf(rx1, fmaxf(sacc[j][2], sacc[j][3]));
        }
        rx0 = fmaxf(rx0, __shfl_xor_sync(0xffffffffu, rx0, 1));
        rx0 = fmaxf(rx0, __shfl_xor_sync(0xffffffffu, rx0, 2));
        rx1 = fmaxf(rx1, __shfl_xor_sync(0xffffffffu, rx1, 1));
        rx1 = fmaxf(rx1, __shfl_xor_sync(0xffffffffu, rx1, 2));
        const float mn0 = fmaxf(m0r, rx0), mn1 = fmaxf(m1r, rx1);
        const float al0 = __expf(m0r - mn0), al1 = __expf(m1r - mn1);
        m0r = mn0; m1r = mn1;

        float rs0 = 0.0f, rs1 = 0.0f;
        uint32_t pH[32], pL[32];
#pragma unroll
        for (int j = 0; j < 16; j++) {
            const float p0 = __expf(sacc[j][0] - mn0);
            const float p1 = __expf(sacc[j][1] - mn0);
            const float p2 = __expf(sacc[j][2] - mn1);
            const float p3 = __expf(sacc[j][3] - mn1);
            rs0 += p0 + p1; rs1 += p2 + p3;
            split2(p0, p1, pH[2 * j],     pL[2 * j]);
            split2(p2, p3, pH[2 * j + 1], pL[2 * j + 1]);
        }
        rs0 += __shfl_xor_sync(0xffffffffu, rs0, 1);
        rs0 += __shfl_xor_sync(0xffffffffu, rs0, 2);
        rs1 += __shfl_xor_sync(0xffffffffu, rs1, 1);
        rs1 += __shfl_xor_sync(0xffffffffu, rs1, 2);
        l0r = l0r * al0 + rs0;
        l1r = l1r * al1 + rs1;
#pragma unroll
        for (int jd = 0; jd < 8; jd++) {
            oacc[jd][0] *= al0; oacc[jd][1] *= al0;
            oacc[jd][2] *= al1; oacc[jd][3] *= al1;
        }

        // ---- O += P @ V ----
#pragma unroll
        for (int ks2 = 0; ks2 < 8; ks2++) {
            const uint32_t* ph = &pH[4 * ks2];
            const uint32_t* pl = &pL[4 * ks2];
#pragma unroll
            for (int jdp = 0; jdp < 4; jdp++) {
                uint32_t vh4[4], vl4[4];
                const int vrow = ks2 * 16 + v_row_off;
                const uint32_t va = sb + SM_VH + vrow * 128
                                  + (((2 * jdp + v_cb) ^ sw) << 4);
                ldsm4t(vh4, va);
                ldsm4t(vl4, va + 16384);
                mma16816(oacc[2 * jdp],     ph, &vh4[0]);
                mma16816(oacc[2 * jdp],     ph, &vl4[0]);
                mma16816(oacc[2 * jdp],     pl, &vh4[0]);
                mma16816(oacc[2 * jdp + 1], ph, &vh4[2]);
                mma16816(oacc[2 * jdp + 1], ph, &vl4[2]);
                mma16816(oacc[2 * jdp + 1], pl, &vh4[2]);
            }
        }
    }

    // ---- epilogue: normalize, split to bf16 ctx [b][q][h*64+d] ----
    const float inv0 = 1.0f / l0r, inv1 = 1.0f / l1r;
    const int b_ = bh >> 4, h_ = bh & 15;
    const int q_g = q0 + wid * 16 + g;
    const size_t base0 = ((size_t)(b_ * SQL + q_g)) * DM + h_ * DH;
    const size_t base1 = base0 + (size_t)8 * DM;
#pragma unroll
    for (int jd = 0; jd < 8; jd++) {
        const int dcol = jd * 8 + 2 * tg;
        uint32_t h2, l2;
        split2(oacc[jd][0] * inv0, oacc[jd][1] * inv0, h2, l2);
        *(uint32_t*)(Ch + base0 + dcol) = h2;
        *(uint32_t*)(Cl + base0 + dcol) = l2;
        split2(oacc[jd][2] * inv1, oacc[jd][3] * inv1, h2, l2);
        *(uint32_t*)(Ch + base1 + dcol) = h2;
        *(uint32_t*)(Cl + base1 + dcol) = l2;
    }
}

// ---------------------------------------------------------------------------
extern "C" void kernel_launch(void* const* d_in, const int* in_sizes, int n_in,
                              void* d_out, int out_size)
{
    const float* x1 = (const float*)d_in[0];
    const float* x2 = (const float*)d_in[1];
    const float* Wq = (const float*)d_in[2];
    const float* bq = (const float*)d_in[3];
    const float* Wk = (const float*)d_in[4];
    const float* bk = (const float*)d_in[5];
    const float* Wv = (const float*)d_in[6];
    const float* bv = (const float*)d_in[7];
    const float* Wo = (const float*)d_in[8];
    const float* bo = (const float*)d_in[9];
    float* out = (float*)d_out;

    bf16 *Qh, *Ql, *Kh, *Kl, *Vh, *Vl, *Ah, *Al, *Wh, *Wl;
    cudaGetSymbolAddress((void**)&Qh, g_Qh);
    cudaGetSymbolAddress((void**)&Ql, g_Ql);
    cudaGetSymbolAddress((void**)&Kh, g_Kh);
    cudaGetSymbolAddress((void**)&Kl, g_Kl);
    cudaGetSymbolAddress((void**)&Vh, g_Vh);
    cudaGetSymbolAddress((void**)&Vl, g_Vl);
    cudaGetSymbolAddress((void**)&Ah, g_Ah);
    cudaGetSymbolAddress((void**)&Al, g_Al);
    cudaGetSymbolAddress((void**)&Wh, g_Wh);
    cudaGetSymbolAddress((void**)&Wl, g_Wl);

    cudaFuncSetAttribute(attn_mma,
                         cudaFuncAttributeMaxDynamicSharedMemorySize, 98304);

    const int convA_blocks = (ROWS * DM / 4) / 256;   // 4096
    dim3 wgrid(DM / 32, DM / 32), wblk(32, 32);
    dim3 ggrid(DM / 128, ROWS / 128);                 // (8, 32)

    // Q = (x1 @ Wq + bq) * 0.125  -> split bf16 [bh][q][64]
    convA_kernel<<<convA_blocks, 256>>>(x1, Ah, Al);
    convW_kernel<<<wgrid, wblk>>>(Wq, Wh, Wl);
    gemm_mma<<<ggrid, 256>>>(Ah, Al, Wh, Wl, bq, Qh, Ql, (float*)0, 0.125f);

    // K, V from x2
    convA_kernel<<<convA_blocks, 256>>>(x2, Ah, Al);
    convW_kernel<<<wgrid, wblk>>>(Wk, Wh, Wl);
    gemm_mma<<<ggrid, 256>>>(Ah, Al, Wh, Wl, bk, Kh, Kl, (float*)0, 1.0f);
    convW_kernel<<<wgrid, wblk>>>(Wv, Wh, Wl);
    gemm_mma<<<ggrid, 256>>>(Ah, Al, Wh, Wl, bv, Vh, Vl, (float*)0, 1.0f);

    // attention -> ctx split bf16 written into Ah/Al
    dim3 agrid(SQL / 128, BH);
    attn_mma<<<agrid, 256, 98304>>>(Qh, Ql, Kh, Kl, Vh, Vl, Ah, Al);

    // out = ctx @ Wo + bo  (fp32)
    convW_kernel<<<wgrid, wblk>>>(Wo, Wh, Wl);
    gemm_mma<<<ggrid, 256>>>(Ah, Al, Wh, Wl, bo, (bf16*)0, (bf16*)0, out, 1.0f);
}

// round 4
// speedup vs baseline: 2.5671x; 1.1139x over previous
#include <cuda_runtime.h>
#include <cuda_bf16.h>
#include <math.h>
#include <stdint.h>

#define BB   2
#define SQL  2048
#define DM   1024
#define NH   16
#define DH   64
#define BH   32
#define ROWS 4096

typedef __nv_bfloat16 bf16;

// ---------------- scratch (__device__ globals) -----------------------------
__device__ bf16 g_Qh[BH * SQL * DH];
__device__ bf16 g_Ql[BH * SQL * DH];
__device__ bf16 g_Kh[BH * SQL * DH];
__device__ bf16 g_Kl[BH * SQL * DH];
__device__ bf16 g_Vh[BH * SQL * DH];
__device__ bf16 g_Vl[BH * SQL * DH];
__device__ bf16 g_Ah[ROWS * DM];   // x1 split; later ctx split
__device__ bf16 g_Al[ROWS * DM];
__device__ bf16 g_Bh[ROWS * DM];   // x2 split
__device__ bf16 g_Bl[ROWS * DM];
__device__ bf16 g_Wqh[DM * DM], g_Wql[DM * DM];
__device__ bf16 g_Wkh[DM * DM], g_Wkl[DM * DM];
__device__ bf16 g_Wvh[DM * DM], g_Wvl[DM * DM];
__device__ bf16 g_Woh[DM * DM], g_Wol[DM * DM];

// ---------------- helpers --------------------------------------------------
__device__ __forceinline__ uint32_t smem_to_u32(const void* p) {
    uint32_t a;
    asm("{ .reg .u64 t; cvta.to.shared.u64 t, %1; cvt.u32.u64 %0, t; }"
        : "=r"(a) : "l"(p));
    return a;
}
__device__ __forceinline__ void ldsm4(uint32_t* r, uint32_t a) {
    asm volatile("ldmatrix.sync.aligned.m8n8.x4.shared.b16 {%0,%1,%2,%3}, [%4];"
        : "=r"(r[0]), "=r"(r[1]), "=r"(r[2]), "=r"(r[3]) : "r"(a));
}
__device__ __forceinline__ void ldsm4t(uint32_t* r, uint32_t a) {
    asm volatile("ldmatrix.sync.aligned.m8n8.x4.trans.shared.b16 {%0,%1,%2,%3}, [%4];"
        : "=r"(r[0]), "=r"(r[1]), "=r"(r[2]), "=r"(r[3]) : "r"(a));
}
__device__ __forceinline__ void mma16816(float* c, const uint32_t* a, const uint32_t* b) {
    asm volatile("mma.sync.aligned.m16n8k16.row.col.f32.bf16.bf16.f32 "
        "{%0,%1,%2,%3}, {%4,%5,%6,%7}, {%8,%9}, {%0,%1,%2,%3};"
        : "+f"(c[0]), "+f"(c[1]), "+f"(c[2]), "+f"(c[3])
        : "r"(a[0]), "r"(a[1]), "r"(a[2]), "r"(a[3]), "r"(b[0]), "r"(b[1]));
}
__device__ __forceinline__ void split2(float v0, float v1, uint32_t& hi2, uint32_t& lo2) {
    __nv_bfloat16 b0 = __float2bfloat16_rn(v0), b1 = __float2bfloat16_rn(v1);
    union { __nv_bfloat162 v; uint32_t u; } p;
    p.v.x = b0; p.v.y = b1; hi2 = p.u;
    p.v.x = __float2bfloat16_rn(v0 - __bfloat162float(b0));
    p.v.y = __float2bfloat16_rn(v1 - __bfloat162float(b1));
    lo2 = p.u;
}
__device__ __forceinline__ float ex2(float x) {
    float y; asm("ex2.approx.f32 %0, %1;" : "=f"(y) : "f"(x)); return y;
}
#define CP16(dst, src) \
    asm volatile("cp.async.cg.shared.global [%0], [%1], 16;" :: "r"(dst), "l"(src))
#define CP_COMMIT() asm volatile("cp.async.commit_group;" ::: "memory")
#define CP_WAIT(n)  asm volatile("cp.async.wait_group %0;" :: "n"(n) : "memory")

// ---------------- conversion kernels ---------------------------------------
__global__ __launch_bounds__(256)
void convA_kernel(const float* __restrict__ x, bf16* __restrict__ hi,
                  bf16* __restrict__ lo)
{
    int i = blockIdx.x * 256 + threadIdx.x;
    float4 v = ((const float4*)x)[i];
    uint32_t h0, l0, h1, l1;
    split2(v.x, v.y, h0, l0);
    split2(v.z, v.w, h1, l1);
    ((uint32_t*)hi)[2 * i] = h0; ((uint32_t*)hi)[2 * i + 1] = h1;
    ((uint32_t*)lo)[2 * i] = l0; ((uint32_t*)lo)[2 * i + 1] = l1;
}

struct WArgs { const float* W[3]; bf16* hi[3]; bf16* lo[3]; };
__global__ __launch_bounds__(1024)
void convW_kernel(WArgs a)
{
    const int z = blockIdx.z;
    const float* __restrict__ W = a.W[z];
    bf16* __restrict__ hi = a.hi[z];
    bf16* __restrict__ lo = a.lo[z];
    __shared__ float tile[32][33];
    int tx = threadIdx.x, ty = threadIdx.y;
    int k = blockIdx.y * 32 + ty;
    int n = blockIdx.x * 32 + tx;
    tile[ty][tx] = W[(size_t)k * DM + n];
    __syncthreads();
    int nn = blockIdx.x * 32 + ty;
    int kk = blockIdx.y * 32 + tx;
    float v = tile[tx][ty];
    __nv_bfloat16 h = __float2bfloat16_rn(v);
    hi[(size_t)nn * DM + kk] = h;
    lo[(size_t)nn * DM + kk] = __float2bfloat16_rn(v - __bfloat162float(h));
}

// ---------------- split-bf16 GEMM via mma.sync, cp.async 2-stage -----------
struct GArgs {
    const bf16* Ah[3]; const bf16* Al[3];
    const bf16* Wh[3]; const bf16* Wl[3];
    const float* bias[3];
    bf16* oh[3]; bf16* ol[3];
    float* of[3];
    float scale[3];
};
#define GSTG 40960
__global__ __launch_bounds__(256, 1)
void gemm_mma(GArgs ar)
{
    extern __shared__ __align__(16) char dsm[];
    const int z = blockIdx.z;
    const bf16* __restrict__ Ah = ar.Ah[z];
    const bf16* __restrict__ Al = ar.Al[z];
    const bf16* __restrict__ Bh = ar.Wh[z];
    const bf16* __restrict__ Bl = ar.Wl[z];
    const float* __restrict__ bias = ar.bias[z];
    const float scale = ar.scale[z];

    const uint32_t sb0 = smem_to_u32(dsm);
    const int t = threadIdx.x, L = t & 31, wid = t >> 5;
    const int wm = wid >> 2, wn = wid & 3;
    const int m0 = blockIdx.y * 128, n0 = blockIdx.x * 128;

    const int r0 = t >> 2, c0 = t & 3;
    // copy one stage: A/B hi/lo, rows r0 and r0+64
    auto copy_stage = [&](int st, int k0) {
        const uint32_t d0 = sb0 + st * GSTG + r0 * 80 + c0 * 16;
        const char* gA = (const char*)(Ah + (size_t)(m0 + r0) * DM + k0 + c0 * 8);
        const char* gAl = (const char*)(Al + (size_t)(m0 + r0) * DM + k0 + c0 * 8);
        const char* gB = (const char*)(Bh + (size_t)(n0 + r0) * DM + k0 + c0 * 8);
        const char* gBl = (const char*)(Bl + (size_t)(n0 + r0) * DM + k0 + c0 * 8);
        CP16(d0,                 gA);
        CP16(d0 + 64 * 80,       gA + 128 * DM);
        CP16(d0 + 10240,         gAl);
        CP16(d0 + 10240 + 64*80, gAl + 128 * DM);
        CP16(d0 + 20480,         gB);
        CP16(d0 + 20480 + 64*80, gB + 128 * DM);
        CP16(d0 + 30720,         gBl);
        CP16(d0 + 30720 + 64*80, gBl + 128 * DM);
    };

    float acc[4][4][4];
#pragma unroll
    for (int a = 0; a < 4; a++)
#pragma unroll
        for (int b = 0; b < 4; b++)
#pragma unroll
            for (int c = 0; c < 4; c++) acc[a][b][c] = 0.0f;

    const int a_row_off = ((L >> 3) & 1) * 8 + (L & 7);
    const int a_ch = (L >> 4);
    const int b_row_off = ((L >> 4) & 1) * 8 + (L & 7);
    const int b_ch = ((L >> 3) & 1);

    copy_stage(0, 0);
    CP_COMMIT();

    for (int kt = 0; kt < 32; kt++) {
        const int cur = kt & 1;
        if (kt < 31) { copy_stage(1 - cur, (kt + 1) * 32); CP_COMMIT(); CP_WAIT(1); }
        else CP_WAIT(0);
        __syncthreads();
        const uint32_t sb = sb0 + cur * GSTG;
#pragma unroll
        for (int ks = 0; ks < 2; ks++) {
            uint32_t aH[4][4], aL[4][4], bHf[2][4], bLf[2][4];
            const int ach = (2 * ks + a_ch) * 16;
#pragma unroll
            for (int mt = 0; mt < 4; mt++) {
                const uint32_t ad = sb + (wm * 64 + mt * 16 + a_row_off) * 80 + ach;
                ldsm4(aH[mt], ad);
                ldsm4(aL[mt], ad + 10240);
            }
            const int bch = (2 * ks + b_ch) * 16;
#pragma unroll
            for (int np = 0; np < 2; np++) {
                const uint32_t bd = sb + 20480 + (wn * 32 + np * 16 + b_row_off) * 80 + bch;
                ldsm4(bHf[np], bd);
                ldsm4(bLf[np], bd + 10240);
            }
#pragma unroll
            for (int mt = 0; mt < 4; mt++)
#pragma unroll
                for (int nt = 0; nt < 4; nt++) {
                    const uint32_t* bh_ = &bHf[nt >> 1][(nt & 1) * 2];
                    const uint32_t* bl_ = &bLf[nt >> 1][(nt & 1) * 2];
                    mma16816(acc[mt][nt], aH[mt], bh_);
                    mma16816(acc[mt][nt], aH[mt], bl_);
                    mma16816(acc[mt][nt], aL[mt], bh_);
                }
        }
        __syncthreads();
    }

    // epilogue
    bf16* __restrict__ outH = ar.oh[z];
    bf16* __restrict__ outL = ar.ol[z];
    float* __restrict__ outF = ar.of[z];
    const int g = L >> 2, tg = L & 3;
#pragma unroll
    for (int mt = 0; mt < 4; mt++) {
#pragma unroll
        for (int nt = 0; nt < 4; nt++) {
            const int mrow = m0 + wm * 64 + mt * 16 + g;
            const int ncol = n0 + wn * 32 + nt * 8 + 2 * tg;
            const float b0v = bias[ncol], b1v = bias[ncol + 1];
            const float v00 = (acc[mt][nt][0] + b0v) * scale;
            const float v01 = (acc[mt][nt][1] + b1v) * scale;
            const float v10 = (acc[mt][nt][2] + b0v) * scale;
            const float v11 = (acc[mt][nt][3] + b1v) * scale;
            if (outF) {
                *(float2*)(outF + (size_t)mrow * DM + ncol) = make_float2(v00, v01);
                *(float2*)(outF + (size_t)(mrow + 8) * DM + ncol) = make_float2(v10, v11);
            } else {
                const int b_ = mrow >> 11, s_ = mrow & 2047;
                const int h_ = ncol >> 6, d_ = ncol & 63;
                const size_t oi = ((size_t)(b_ * NH + h_) * SQL + s_) * DH + d_;
                uint32_t h2, l2;
                split2(v00, v01, h2, l2);
                *(uint32_t*)(outH + oi) = h2;
                *(uint32_t*)(outL + oi) = l2;
                split2(v10, v11, h2, l2);
                *(uint32_t*)(outH + oi + 8 * DH) = h2;
                *(uint32_t*)(outL + oi + 8 * DH) = l2;
            }
        }
    }
}

// ---------------- flash attention, cp.async 2-stage, Q frags in regs -------
// smem: QH 0, QL 16384; stages at 32768 (stride 65536): KH 0, KL 16K, VH 32K, VL 48K
#define A_SMEM  163840
#define ASTG_B  32768
#define ASTG_S  65536
__global__ __launch_bounds__(256, 1)
void attn_mma(const bf16* __restrict__ Qh, const bf16* __restrict__ Ql,
              const bf16* __restrict__ Kh, const bf16* __restrict__ Kl,
              const bf16* __restrict__ Vh, const bf16* __restrict__ Vl,
              bf16* __restrict__ Ch, bf16* __restrict__ Cl)
{
    extern __shared__ __align__(16) char sm_[];
    const uint32_t sb = smem_to_u32(sm_);
    const int t = threadIdx.x, L = t & 31, wid = t >> 5;
    const int bh = blockIdx.y, q0 = blockIdx.x * 128;
    const int g = L >> 2, tg = L & 3;

    const int a_row = wid * 16 + ((L >> 3) & 1) * 8 + (L & 7);
    const int a_cb  = (L >> 4);
    const int k_row_off = ((L >> 4) & 1) * 8 + (L & 7);
    const int k_cb  = ((L >> 3) & 1);
    const int v_row_off = ((L >> 3) & 1) * 8 + (L & 7);
    const int v_cb  = (L >> 4);
    const int sw    = L & 7;

    // ---- Q load via cp.async, then hoist fragments into registers ----
    {
        const char* qh = (const char*)(Qh + ((size_t)bh * SQL + q0) * DH);
        const char* ql = (const char*)(Ql + ((size_t)bh * SQL + q0) * DH);
#pragma unroll
        for (int i = 0; i < 4; i++) {
            const int u = t + i * 256, r = u >> 3, c = u & 7;
            const uint32_t so = r * 128 + ((c ^ (r & 7)) << 4);
            const int go = r * 128 + c * 16;
            CP16(sb + so,         qh + go);
            CP16(sb + 16384 + so, ql + go);
        }
        CP_COMMIT();
    }
    uint32_t qH[4][4], qL[4][4];
    CP_WAIT(0);
    __syncthreads();
#pragma unroll
    for (int ks = 0; ks < 4; ks++) {
        const uint32_t qa = sb + a_row * 128 + (((2 * ks + a_cb) ^ sw) << 4);
        ldsm4(qH[ks], qa);
        ldsm4(qL[ks], qa + 16384);
    }

    auto copy_kv = [&](int st, int kb) {
        const uint32_t base = sb + ASTG_B + st * ASTG_S;
        const size_t goff = ((size_t)bh * SQL + kb * 128) * DH;
        const char* kh = (const char*)(Kh + goff);
        const char* kl = (const char*)(Kl + goff);
        const char* vh = (const char*)(Vh + goff);
        const char* vl = (const char*)(Vl + goff);
#pragma unroll
        for (int i = 0; i < 4; i++) {
            const int u = t + i * 256, r = u >> 3, c = u & 7;
            const uint32_t so = r * 128 + ((c ^ (r & 7)) << 4);
            const int go = r * 128 + c * 16;
            CP16(base + so,         kh + go);
            CP16(base + 16384 + so, kl + go);
            CP16(base + 32768 + so, vh + go);
            CP16(base + 49152 + so, vl + go);
        }
    };

    float oacc[8][4];
#pragma unroll
    for (int a = 0; a < 8; a++)
#pragma unroll
        for (int b = 0; b < 4; b++) oacc[a][b] = 0.0f;
    float m0r = -1e30f, m1r = -1e30f, l0r = 0.0f, l1r = 0.0f;

    copy_kv(0, 0);
    CP_COMMIT();

    for (int kb = 0; kb < 16; kb++) {
        const int cur = kb & 1;
        if (kb < 15) { copy_kv(1 - cur, kb + 1); CP_COMMIT(); CP_WAIT(1); }
        else CP_WAIT(0);
        __syncthreads();
        const uint32_t kbase = sb + ASTG_B + cur * ASTG_S;

        // ---- S = Q @ K^T (log2 domain; 0.125*log2e folded into Q) ----
        float sacc[16][4];
#pragma unroll
        for (int j = 0; j < 16; j++)
#pragma unroll
            for (int c = 0; c < 4; c++) sacc[j][c] = 0.0f;

#pragma unroll
        for (int ks = 0; ks < 4; ks++) {
#pragma unroll
            for (int jp = 0; jp < 8; jp++) {
                uint32_t kh4[4], kl4[4];
                const int krow = jp * 16 + k_row_off;
                const uint32_t ka = kbase + krow * 128 + (((2 * ks + k_cb) ^ sw) << 4);
                ldsm4(kh4, ka);
                ldsm4(kl4, ka + 16384);
                mma16816(sacc[2 * jp],     qH[ks], &kh4[0]);
                mma16816(sacc[2 * jp],     qH[ks], &kl4[0]);
                mma16816(sacc[2 * jp],     qL[ks], &kh4[0]);
                mma16816(sacc[2 * jp + 1], qH[ks], &kh4[2]);
                mma16816(sacc[2 * jp + 1], qH[ks], &kl4[2]);
                mma16816(sacc[2 * jp + 1], qL[ks], &kh4[2]);
            }
        }

        // ---- online softmax (exp2 domain), P written back into sacc ----
        float rx0 = -1e30f, rx1 = -1e30f;
#pragma unroll
        for (int j = 0; j < 16; j++) {
            rx0 = fmaxf(rx0, fmaxf(sacc[j][0], sacc[j][1]));
            rx1 = fmaxf(rx1, fmaxf(sacc[j][2], sacc[j][3]));
        }
        rx0 = fmaxf(rx0, __shfl_xor_sync(0xffffffffu, rx0, 1));
        rx0 = fmaxf(rx0, __shfl_xor_sync(0xffffffffu, rx0, 2));
        rx1 = fmaxf(rx1, __shfl_xor_sync(0xffffffffu, rx1, 1));
        rx1 = fmaxf(rx1, __shfl_xor_sync(0xffffffffu, rx1, 2));
        const float mn0 = fmaxf(m0r, rx0), mn1 = fmaxf(m1r, rx1);
        const float al0 = ex2(m0r - mn0), al1 = ex2(m1r - mn1);
        m0r = mn0; m1r = mn1;

        float rs0 = 0.0f, rs1 = 0.0f;
#pragma unroll
        for (int j = 0; j < 16; j++) {
            const float p0 = ex2(sacc[j][0] - mn0);
            const float p1 = ex2(sacc[j][1] - mn0);
            const float p2 = ex2(sacc[j][2] - mn1);
            const float p3 = ex2(sacc[j][3] - mn1);
            sacc[j][0] = p0; sacc[j][1] = p1; sacc[j][2] = p2; sacc[j][3] = p3;
            rs0 += p0 + p1; rs1 += p2 + p3;
        }
        rs0 += __shfl_xor_sync(0xffffffffu, rs0, 1);
        rs0 += __shfl_xor_sync(0xffffffffu, rs0, 2);
        rs1 += __shfl_xor_sync(0xffffffffu, rs1, 1);
        rs1 += __shfl_xor_sync(0xffffffffu, rs1, 2);
        l0r = l0r * al0 + rs0;
        l1r = l1r * al1 + rs1;
#pragma unroll
        for (int jd = 0; jd < 8; jd++) {
            oacc[jd][0] *= al0; oacc[jd][1] *= al0;
            oacc[jd][2] *= al1; oacc[jd][3] *= al1;
        }

        // ---- O += P @ V (split P on the fly) ----
#pragma unroll
        for (int ks2 = 0; ks2 < 8; ks2++) {
            uint32_t ph[4], pl[4];
            split2(sacc[2 * ks2][0],     sacc[2 * ks2][1],     ph[0], pl[0]);
            split2(sacc[2 * ks2][2],     sacc[2 * ks2][3],     ph[1], pl[1]);
            split2(sacc[2 * ks2 + 1][0], sacc[2 * ks2 + 1][1], ph[2], pl[2]);
            split2(sacc[2 * ks2 + 1][2], sacc[2 * ks2 + 1][3], ph[3], pl[3]);
#pragma unroll
            for (int jdp = 0; jdp < 4; jdp++) {
                uint32_t vh4[4], vl4[4];
                const int vrow = ks2 * 16 + v_row_off;
                const uint32_t va = kbase + 32768 + vrow * 128
                                  + (((2 * jdp + v_cb) ^ sw) << 4);
                ldsm4t(vh4, va);
                ldsm4t(vl4, va + 16384);
                mma16816(oacc[2 * jdp],     ph, &vh4[0]);
                mma16816(oacc[2 * jdp],     ph, &vl4[0]);
                mma16816(oacc[2 * jdp],     pl, &vh4[0]);
                mma16816(oacc[2 * jdp + 1], ph, &vh4[2]);
                mma16816(oacc[2 * jdp + 1], ph, &vl4[2]);
                mma16816(oacc[2 * jdp + 1], pl, &vh4[2]);
            }
        }
        __syncthreads();
    }

    // ---- epilogue: normalize, split to bf16 ctx [b][q][h*64+d] ----
    const float inv0 = 1.0f / l0r, inv1 = 1.0f / l1r;
    const int b_ = bh >> 4, h_ = bh & 15;
    const int q_g = q0 + wid * 16 + g;
    const size_t base0 = ((size_t)(b_ * SQL + q_g)) * DM + h_ * DH;
    const size_t base1 = base0 + (size_t)8 * DM;
#pragma unroll
    for (int jd = 0; jd < 8; jd++) {
        const int dcol = jd * 8 + 2 * tg;
        uint32_t h2, l2;
        split2(oacc[jd][0] * inv0, oacc[jd][1] * inv0, h2, l2);
        *(uint32_t*)(Ch + base0 + dcol) = h2;
        *(uint32_t*)(Cl + base0 + dcol) = l2;
        split2(oacc[jd][2] * inv1, oacc[jd][3] * inv1, h2, l2);
        *(uint32_t*)(Ch + base1 + dcol) = h2;
        *(uint32_t*)(Cl + base1 + dcol) = l2;
    }
}

// ---------------------------------------------------------------------------
extern "C" void kernel_launch(void* const* d_in, const int* in_sizes, int n_in,
                              void* d_out, int out_size)
{
    const float* x1 = (const float*)d_in[0];
    const float* x2 = (const float*)d_in[1];
    const float* Wq = (const float*)d_in[2];
    const float* bq = (const float*)d_in[3];
    const float* Wk = (const float*)d_in[4];
    const float* bk = (const float*)d_in[5];
    const float* Wv = (const float*)d_in[6];
    const float* bv = (const float*)d_in[7];
    const float* Wo = (const float*)d_in[8];
    const float* bo = (const float*)d_in[9];
    float* out = (float*)d_out;

    bf16 *Qh, *Ql, *Kh, *Kl, *Vh, *Vl, *Ah, *Al, *Bh, *Bl;
    bf16 *Wqh, *Wql, *Wkh, *Wkl, *Wvh, *Wvl, *Woh, *Wol;
    cudaGetSymbolAddress((void**)&Qh, g_Qh);  cudaGetSymbolAddress((void**)&Ql, g_Ql);
    cudaGetSymbolAddress((void**)&Kh, g_Kh);  cudaGetSymbolAddress((void**)&Kl, g_Kl);
    cudaGetSymbolAddress((void**)&Vh, g_Vh);  cudaGetSymbolAddress((void**)&Vl, g_Vl);
    cudaGetSymbolAddress((void**)&Ah, g_Ah);  cudaGetSymbolAddress((void**)&Al, g_Al);
    cudaGetSymbolAddress((void**)&Bh, g_Bh);  cudaGetSymbolAddress((void**)&Bl, g_Bl);
    cudaGetSymbolAddress((void**)&Wqh, g_Wqh); cudaGetSymbolAddress((void**)&Wql, g_Wql);
    cudaGetSymbolAddress((void**)&Wkh, g_Wkh); cudaGetSymbolAddress((void**)&Wkl, g_Wkl);
    cudaGetSymbolAddress((void**)&Wvh, g_Wvh); cudaGetSymbolAddress((void**)&Wvl, g_Wvl);
    cudaGetSymbolAddress((void**)&Woh, g_Woh); cudaGetSymbolAddress((void**)&Wol, g_Wol);

    cudaFuncSetAttribute(attn_mma,
                         cudaFuncAttributeMaxDynamicSharedMemorySize, A_SMEM);
    cudaFuncSetAttribute(gemm_mma,
                         cudaFuncAttributeMaxDynamicSharedMemorySize, 2 * GSTG);

    const int convA_blocks = (ROWS * DM / 4) / 256;
    const float qscale = 0.125f * 1.4426950408889634f;   // 1/sqrt(64) * log2(e)

    // splits
    convA_kernel<<<convA_blocks, 256>>>(x1, Ah, Al);
    convA_kernel<<<convA_blocks, 256>>>(x2, Bh, Bl);
    {
        WArgs wa;
        wa.W[0] = Wq; wa.hi[0] = Wqh; wa.lo[0] = Wql;
        wa.W[1] = Wk; wa.hi[1] = Wkh; wa.lo[1] = Wkl;
        wa.W[2] = Wv; wa.hi[2] = Wvh; wa.lo[2] = Wvl;
        convW_kernel<<<dim3(DM/32, DM/32, 3), dim3(32, 32)>>>(wa);
    }
    {
        WArgs wa;
        wa.W[0] = Wo; wa.hi[0] = Woh; wa.lo[0] = Wol;
        wa.W[1] = Wo; wa.hi[1] = Woh; wa.lo[1] = Wol;
        wa.W[2] = Wo; wa.hi[2] = Woh; wa.lo[2] = Wol;
        convW_kernel<<<dim3(DM/32, DM/32, 1), dim3(32, 32)>>>(wa);
    }

    // fused QKV projections
    {
        GArgs ga;
        ga.Ah[0] = Ah; ga.Al[0] = Al; ga.Wh[0] = Wqh; ga.Wl[0] = Wql;
        ga.bias[0] = bq; ga.oh[0] = Qh; ga.ol[0] = Ql; ga.of[0] = 0; ga.scale[0] = qscale;
        ga.Ah[1] = Bh; ga.Al[1] = Bl; ga.Wh[1] = Wkh; ga.Wl[1] = Wkl;
        ga.bias[1] = bk; ga.oh[1] = Kh; ga.ol[1] = Kl; ga.of[1] = 0; ga.scale[1] = 1.0f;
        ga.Ah[2] = Bh; ga.Al[2] = Bl; ga.Wh[2] = Wvh; ga.Wl[2] = Wvl;
        ga.bias[2] = bv; ga.oh[2] = Vh; ga.ol[2] = Vl; ga.of[2] = 0; ga.scale[2] = 1.0f;
        gemm_mma<<<dim3(DM/128, ROWS/128, 3), 256, 2 * GSTG>>>(ga);
    }

    // attention -> ctx split (overwrites Ah/Al)
    attn_mma<<<dim3(SQL/128, BH), 256, A_SMEM>>>(Qh, Ql, Kh, Kl, Vh, Vl, Ah, Al);

    // out = ctx @ Wo + bo (fp32)
    {
        GArgs ga;
        ga.Ah[0] = Ah; ga.Al[0] = Al; ga.Wh[0] = Woh; ga.Wl[0] = Wol;
        ga.bias[0] = bo; ga.oh[0] = 0; ga.ol[0] = 0; ga.of[0] = out; ga.scale[0] = 1.0f;
        gemm_mma<<<dim3(DM/128, ROWS/128, 1), 256, 2 * GSTG>>>(ga);
    }
}

// round 5
// speedup vs baseline: 2.6584x; 1.0356x over previous
#include <cuda_runtime.h>
#include <cuda_bf16.h>
#include <math.h>
#include <stdint.h>

#define BB   2
#define SQL  2048
#define DM   1024
#define NH   16
#define DH   64
#define BH   32
#define ROWS 4096

typedef __nv_bfloat16 bf16;

// ---------------- scratch (__device__ globals) -----------------------------
__device__ bf16 g_Qh[BH * SQL * DH];
__device__ bf16 g_Ql[BH * SQL * DH];
__device__ bf16 g_Kh[BH * SQL * DH];
__device__ bf16 g_Kl[BH * SQL * DH];
__device__ bf16 g_Vh[BH * SQL * DH];
__device__ bf16 g_Vl[BH * SQL * DH];
__device__ bf16 g_Ah[ROWS * DM];   // x1 split; later ctx split
__device__ bf16 g_Al[ROWS * DM];
__device__ bf16 g_Bh[ROWS * DM];   // x2 split
__device__ bf16 g_Bl[ROWS * DM];
__device__ bf16 g_Wqh[DM * DM], g_Wql[DM * DM];
__device__ bf16 g_Wkh[DM * DM], g_Wkl[DM * DM];
__device__ bf16 g_Wvh[DM * DM], g_Wvl[DM * DM];
__device__ bf16 g_Woh[DM * DM], g_Wol[DM * DM];

// ---------------- helpers --------------------------------------------------
__device__ __forceinline__ uint32_t smem_to_u32(const void* p) {
    uint32_t a;
    asm("{ .reg .u64 t; cvta.to.shared.u64 t, %1; cvt.u32.u64 %0, t; }"
        : "=r"(a) : "l"(p));
    return a;
}
__device__ __forceinline__ void ldsm4(uint32_t* r, uint32_t a) {
    asm volatile("ldmatrix.sync.aligned.m8n8.x4.shared.b16 {%0,%1,%2,%3}, [%4];"
        : "=r"(r[0]), "=r"(r[1]), "=r"(r[2]), "=r"(r[3]) : "r"(a));
}
__device__ __forceinline__ void ldsm4t(uint32_t* r, uint32_t a) {
    asm volatile("ldmatrix.sync.aligned.m8n8.x4.trans.shared.b16 {%0,%1,%2,%3}, [%4];"
        : "=r"(r[0]), "=r"(r[1]), "=r"(r[2]), "=r"(r[3]) : "r"(a));
}
__device__ __forceinline__ void mma16816(float* c, const uint32_t* a, const uint32_t* b) {
    asm volatile("mma.sync.aligned.m16n8k16.row.col.f32.bf16.bf16.f32 "
        "{%0,%1,%2,%3}, {%4,%5,%6,%7}, {%8,%9}, {%0,%1,%2,%3};"
        : "+f"(c[0]), "+f"(c[1]), "+f"(c[2]), "+f"(c[3])
        : "r"(a[0]), "r"(a[1]), "r"(a[2]), "r"(a[3]), "r"(b[0]), "r"(b[1]));
}
__device__ __forceinline__ void split2(float v0, float v1, uint32_t& hi2, uint32_t& lo2) {
    __nv_bfloat16 b0 = __float2bfloat16_rn(v0), b1 = __float2bfloat16_rn(v1);
    union { __nv_bfloat162 v; uint32_t u; } p;
    p.v.x = b0; p.v.y = b1; hi2 = p.u;
    p.v.x = __float2bfloat16_rn(v0 - __bfloat162float(b0));
    p.v.y = __float2bfloat16_rn(v1 - __bfloat162float(b1));
    lo2 = p.u;
}
__device__ __forceinline__ float ex2(float x) {
    float y; asm("ex2.approx.f32 %0, %1;" : "=f"(y) : "f"(x)); return y;
}
#define CP16(dst, src) \
    asm volatile("cp.async.cg.shared.global [%0], [%1], 16;" :: "r"(dst), "l"(src))
#define CP_COMMIT() asm volatile("cp.async.commit_group;" ::: "memory")
#define CP_WAIT(n)  asm volatile("cp.async.wait_group %0;" :: "n"(n) : "memory")

// ---------------- conversion kernels ---------------------------------------
__global__ __launch_bounds__(256)
void convA_kernel(const float* __restrict__ x1, bf16* __restrict__ hi1,
                  bf16* __restrict__ lo1,
                  const float* __restrict__ x2, bf16* __restrict__ hi2v,
                  bf16* __restrict__ lo2v, int half)
{
    int bi = blockIdx.x;
    const float* x; bf16 *hi, *lo;
    if (bi < half) { x = x1; hi = hi1; lo = lo1; }
    else           { x = x2; hi = hi2v; lo = lo2v; bi -= half; }
    int i = bi * 256 + threadIdx.x;
    float4 v = ((const float4*)x)[i];
    uint32_t h0, l0, h1, l1;
    split2(v.x, v.y, h0, l0);
    split2(v.z, v.w, h1, l1);
    ((uint32_t*)hi)[2 * i] = h0; ((uint32_t*)hi)[2 * i + 1] = h1;
    ((uint32_t*)lo)[2 * i] = l0; ((uint32_t*)lo)[2 * i + 1] = l1;
}

struct WArgs { const float* W[4]; bf16* hi[4]; bf16* lo[4]; };
__global__ __launch_bounds__(1024)
void convW_kernel(WArgs a)
{
    const int z = blockIdx.z;
    const float* __restrict__ W = a.W[z];
    bf16* __restrict__ hi = a.hi[z];
    bf16* __restrict__ lo = a.lo[z];
    __shared__ float tile[32][33];
    int tx = threadIdx.x, ty = threadIdx.y;
    int k = blockIdx.y * 32 + ty;
    int n = blockIdx.x * 32 + tx;
    tile[ty][tx] = W[(size_t)k * DM + n];
    __syncthreads();
    int nn = blockIdx.x * 32 + ty;
    int kk = blockIdx.y * 32 + tx;
    float v = tile[tx][ty];
    __nv_bfloat16 h = __float2bfloat16_rn(v);
    hi[(size_t)nn * DM + kk] = h;
    lo[(size_t)nn * DM + kk] = __float2bfloat16_rn(v - __bfloat162float(h));
}

// ---------------- split-bf16 GEMM via mma.sync, cp.async 2-stage -----------
struct GArgs {
    const bf16* Ah[3]; const bf16* Al[3];
    const bf16* Wh[3]; const bf16* Wl[3];
    const float* bias[3];
    bf16* oh[3]; bf16* ol[3];
    float* of[3];
    float scale[3];
};
#define GSTG 40960
__global__ __launch_bounds__(256, 1)
void gemm_mma(GArgs ar)
{
    extern __shared__ __align__(16) char dsm[];
    const int z = blockIdx.z;
    const bf16* __restrict__ Ah = ar.Ah[z];
    const bf16* __restrict__ Al = ar.Al[z];
    const bf16* __restrict__ Bh = ar.Wh[z];
    const bf16* __restrict__ Bl = ar.Wl[z];
    const float* __restrict__ bias = ar.bias[z];
    const float scale = ar.scale[z];

    const uint32_t sb0 = smem_to_u32(dsm);
    const int t = threadIdx.x, L = t & 31, wid = t >> 5;
    const int wm = wid >> 2, wn = wid & 3;
    const int m0 = blockIdx.y * 128, n0 = blockIdx.x * 128;

    const int r0 = t >> 2, c0 = t & 3;
    auto copy_stage = [&](int st, int k0) {
        const uint32_t d0 = sb0 + st * GSTG + r0 * 80 + c0 * 16;
        const char* gA = (const char*)(Ah + (size_t)(m0 + r0) * DM + k0 + c0 * 8);
        const char* gAl = (const char*)(Al + (size_t)(m0 + r0) * DM + k0 + c0 * 8);
        const char* gB = (const char*)(Bh + (size_t)(n0 + r0) * DM + k0 + c0 * 8);
        const char* gBl = (const char*)(Bl + (size_t)(n0 + r0) * DM + k0 + c0 * 8);
        CP16(d0,                 gA);
        CP16(d0 + 64 * 80,       gA + 128 * DM);
        CP16(d0 + 10240,         gAl);
        CP16(d0 + 10240 + 64*80, gAl + 128 * DM);
        CP16(d0 + 20480,         gB);
        CP16(d0 + 20480 + 64*80, gB + 128 * DM);
        CP16(d0 + 30720,         gBl);
        CP16(d0 + 30720 + 64*80, gBl + 128 * DM);
    };

    float acc[4][4][4];
#pragma unroll
    for (int a = 0; a < 4; a++)
#pragma unroll
        for (int b = 0; b < 4; b++)
#pragma unroll
            for (int c = 0; c < 4; c++) acc[a][b][c] = 0.0f;

    const int a_row_off = ((L >> 3) & 1) * 8 + (L & 7);
    const int a_ch = (L >> 4);
    const int b_row_off = ((L >> 4) & 1) * 8 + (L & 7);
    const int b_ch = ((L >> 3) & 1);

    copy_stage(0, 0);
    CP_COMMIT();

    for (int kt = 0; kt < 32; kt++) {
        const int cur = kt & 1;
        if (kt < 31) { copy_stage(1 - cur, (kt + 1) * 32); CP_COMMIT(); CP_WAIT(1); }
        else CP_WAIT(0);
        __syncthreads();
        const uint32_t sb = sb0 + cur * GSTG;
#pragma unroll
        for (int ks = 0; ks < 2; ks++) {
            uint32_t aH[4][4], aL[4][4], bHf[2][4], bLf[2][4];
            const int ach = (2 * ks + a_ch) * 16;
#pragma unroll
            for (int mt = 0; mt < 4; mt++) {
                const uint32_t ad = sb + (wm * 64 + mt * 16 + a_row_off) * 80 + ach;
                ldsm4(aH[mt], ad);
                ldsm4(aL[mt], ad + 10240);
            }
            const int bch = (2 * ks + b_ch) * 16;
#pragma unroll
            for (int np = 0; np < 2; np++) {
                const uint32_t bd = sb + 20480 + (wn * 32 + np * 16 + b_row_off) * 80 + bch;
                ldsm4(bHf[np], bd);
                ldsm4(bLf[np], bd + 10240);
            }
#pragma unroll
            for (int mt = 0; mt < 4; mt++)
#pragma unroll
                for (int nt = 0; nt < 4; nt++) {
                    const uint32_t* bh_ = &bHf[nt >> 1][(nt & 1) * 2];
                    const uint32_t* bl_ = &bLf[nt >> 1][(nt & 1) * 2];
                    mma16816(acc[mt][nt], aH[mt], bh_);
                    mma16816(acc[mt][nt], aH[mt], bl_);
                    mma16816(acc[mt][nt], aL[mt], bh_);
                }
        }
        __syncthreads();
    }

    bf16* __restrict__ outH = ar.oh[z];
    bf16* __restrict__ outL = ar.ol[z];
    float* __restrict__ outF = ar.of[z];
    const int g = L >> 2, tg = L & 3;
#pragma unroll
    for (int mt = 0; mt < 4; mt++) {
#pragma unroll
        for (int nt = 0; nt < 4; nt++) {
            const int mrow = m0 + wm * 64 + mt * 16 + g;
            const int ncol = n0 + wn * 32 + nt * 8 + 2 * tg;
            const float b0v = bias[ncol], b1v = bias[ncol + 1];
            const float v00 = (acc[mt][nt][0] + b0v) * scale;
            const float v01 = (acc[mt][nt][1] + b1v) * scale;
            const float v10 = (acc[mt][nt][2] + b0v) * scale;
            const float v11 = (acc[mt][nt][3] + b1v) * scale;
            if (outF) {
                *(float2*)(outF + (size_t)mrow * DM + ncol) = make_float2(v00, v01);
                *(float2*)(outF + (size_t)(mrow + 8) * DM + ncol) = make_float2(v10, v11);
            } else {
                const int b_ = mrow >> 11, s_ = mrow & 2047;
                const int h_ = ncol >> 6, d_ = ncol & 63;
                const size_t oi = ((size_t)(b_ * NH + h_) * SQL + s_) * DH + d_;
                uint32_t h2, l2;
                split2(v00, v01, h2, l2);
                *(uint32_t*)(outH + oi) = h2;
                *(uint32_t*)(outL + oi) = l2;
                split2(v10, v11, h2, l2);
                *(uint32_t*)(outH + oi + 8 * DH) = h2;
                *(uint32_t*)(outL + oi + 8 * DH) = l2;
            }
        }
    }
}

// ---------------- flash attention: q-tile 64, k-tile 64, 128 thr, 2 CTA/SM -
// smem: QH 0 (8K), QL 8192; stages at 16384 (stride 32768):
//       KH +0, KL +8192, VH +16384, VL +24576.   total 81920 B
#define A_SMEM  81920
#define ASTG_B  16384
#define ASTG_S  32768
__global__ __launch_bounds__(128, 2)
void attn_mma(const bf16* __restrict__ Qh, const bf16* __restrict__ Ql,
              const bf16* __restrict__ Kh, const bf16* __restrict__ Kl,
              const bf16* __restrict__ Vh, const bf16* __restrict__ Vl,
              bf16* __restrict__ Ch, bf16* __restrict__ Cl)
{
    extern __shared__ __align__(16) char sm_[];
    const uint32_t sb = smem_to_u32(sm_);
    const int t = threadIdx.x, L = t & 31, wid = t >> 5;
    const int bh = blockIdx.y, q0 = blockIdx.x * 64;
    const int g = L >> 2, tg = L & 3;

    const int a_row = wid * 16 + ((L >> 3) & 1) * 8 + (L & 7);
    const int a_cb  = (L >> 4);
    const int k_row_off = ((L >> 4) & 1) * 8 + (L & 7);
    const int k_cb  = ((L >> 3) & 1);
    const int v_row_off = ((L >> 3) & 1) * 8 + (L & 7);
    const int v_cb  = (L >> 4);
    const int sw    = L & 7;

    auto copy_kv = [&](int st, int kb) {
        const uint32_t base = sb + ASTG_B + st * ASTG_S;
        const size_t goff = ((size_t)bh * SQL + kb * 64) * DH;
        const char* kh = (const char*)(Kh + goff);
        const char* kl = (const char*)(Kl + goff);
        const char* vh = (const char*)(Vh + goff);
        const char* vl = (const char*)(Vl + goff);
#pragma unroll
        for (int i = 0; i < 4; i++) {
            const int u = t + i * 128, r = u >> 3, c = u & 7;
            const uint32_t so = r * 128 + ((c ^ (r & 7)) << 4);
            const int go = r * 128 + c * 16;
            CP16(base + so,         kh + go);
            CP16(base + 8192 + so,  kl + go);
            CP16(base + 16384 + so, vh + go);
            CP16(base + 24576 + so, vl + go);
        }
    };

    // overlap: first K/V stage, then Q; one wait covers both
    copy_kv(0, 0);
    {
        const char* qh = (const char*)(Qh + ((size_t)bh * SQL + q0) * DH);
        const char* ql = (const char*)(Ql + ((size_t)bh * SQL + q0) * DH);
#pragma unroll
        for (int i = 0; i < 4; i++) {
            const int u = t + i * 128, r = u >> 3, c = u & 7;
            const uint32_t so = r * 128 + ((c ^ (r & 7)) << 4);
            const int go = r * 128 + c * 16;
            CP16(sb + so,        qh + go);
            CP16(sb + 8192 + so, ql + go);
        }
    }
    CP_COMMIT();
    CP_WAIT(0);
    __syncthreads();

    uint32_t qH[4][4], qL[4][4];
#pragma unroll
    for (int ks = 0; ks < 4; ks++) {
        const uint32_t qa = sb + a_row * 128 + (((2 * ks + a_cb) ^ sw) << 4);
        ldsm4(qH[ks], qa);
        ldsm4(qL[ks], qa + 8192);
    }

    float oacc[8][4];
#pragma unroll
    for (int a = 0; a < 8; a++)
#pragma unroll
        for (int b = 0; b < 4; b++) oacc[a][b] = 0.0f;
    float m0r = -1e30f, m1r = -1e30f, l0r = 0.0f, l1r = 0.0f;

    for (int kb = 0; kb < 32; kb++) {
        const int cur = kb & 1;
        if (kb < 31) { copy_kv(1 - cur, kb + 1); CP_COMMIT(); CP_WAIT(1); }
        else CP_WAIT(0);
        __syncthreads();
        const uint32_t kbase = sb + ASTG_B + cur * ASTG_S;

        // ---- S = Q @ K^T (exp2 domain; 0.125*log2e folded into Q) ----
        float sacc[8][4];
#pragma unroll
        for (int j = 0; j < 8; j++)
#pragma unroll
            for (int c = 0; c < 4; c++) sacc[j][c] = 0.0f;

#pragma unroll
        for (int ks = 0; ks < 4; ks++) {
#pragma unroll
            for (int jp = 0; jp < 4; jp++) {
                uint32_t kh4[4], kl4[4];
                const int krow = jp * 16 + k_row_off;
                const uint32_t ka = kbase + krow * 128 + (((2 * ks + k_cb) ^ sw) << 4);
                ldsm4(kh4, ka);
                ldsm4(kl4, ka + 8192);
                mma16816(sacc[2 * jp],     qH[ks], &kh4[0]);
                mma16816(sacc[2 * jp],     qH[ks], &kl4[0]);
                mma16816(sacc[2 * jp],     qL[ks], &kh4[0]);
                mma16816(sacc[2 * jp + 1], qH[ks], &kh4[2]);
                mma16816(sacc[2 * jp + 1], qH[ks], &kl4[2]);
                mma16816(sacc[2 * jp + 1], qL[ks], &kh4[2]);
            }
        }

        // ---- online softmax ----
        float rx0 = -1e30f, rx1 = -1e30f;
#pragma unroll
        for (int j = 0; j < 8; j++) {
            rx0 = fmaxf(rx0, fmaxf(sacc[j][0], sacc[j][1]));
            rx1 = fmaxf(rx1, fmaxf(sacc[j][2], sacc[j][3]));
        }
        rx0 = fmaxf(rx0, __shfl_xor_sync(0xffffffffu, rx0, 1));
        rx0 = fmaxf(rx0, __shfl_xor_sync(0xffffffffu, rx0, 2));
        rx1 = fmaxf(rx1, __shfl_xor_sync(0xffffffffu, rx1, 1));
        rx1 = fmaxf(rx1, __shfl_xor_sync(0xffffffffu, rx1, 2));
        const float mn0 = fmaxf(m0r, rx0), mn1 = fmaxf(m1r, rx1);
        const float al0 = ex2(m0r - mn0), al1 = ex2(m1r - mn1);
        m0r = mn0; m1r = mn1;

        float rs0 = 0.0f, rs1 = 0.0f;
#pragma unroll
        for (int j = 0; j < 8; j++) {
            const float p0 = ex2(sacc[j][0] - mn0);
            const float p1 = ex2(sacc[j][1] - mn0);
            const float p2 = ex2(sacc[j][2] - mn1);
            const float p3 = ex2(sacc[j][3] - mn1);
            sacc[j][0] = p0; sacc[j][1] = p1; sacc[j][2] = p2; sacc[j][3] = p3;
            rs0 += p0 + p1; rs1 += p2 + p3;
        }
        rs0 += __shfl_xor_sync(0xffffffffu, rs0, 1);
        rs0 += __shfl_xor_sync(0xffffffffu, rs0, 2);
        rs1 += __shfl_xor_sync(0xffffffffu, rs1, 1);
        rs1 += __shfl_xor_sync(0xffffffffu, rs1, 2);
        l0r = l0r * al0 + rs0;
        l1r = l1r * al1 + rs1;
#pragma unroll
        for (int jd = 0; jd < 8; jd++) {
            oacc[jd][0] *= al0; oacc[jd][1] *= al0;
            oacc[jd][2] *= al1; oacc[jd][3] *= al1;
        }

        // ---- O += P @ V (split P on the fly) ----
#pragma unroll
        for (int ks2 = 0; ks2 < 4; ks2++) {
            uint32_t ph[4], pl[4];
            split2(sacc[2 * ks2][0],     sacc[2 * ks2][1],     ph[0], pl[0]);
            split2(sacc[2 * ks2][2],     sacc[2 * ks2][3],     ph[1], pl[1]);
            split2(sacc[2 * ks2 + 1][0], sacc[2 * ks2 + 1][1], ph[2], pl[2]);
            split2(sacc[2 * ks2 + 1][2], sacc[2 * ks2 + 1][3], ph[3], pl[3]);
#pragma unroll
            for (int jdp = 0; jdp < 4; jdp++) {
                uint32_t vh4[4], vl4[4];
                const int vrow = ks2 * 16 + v_row_off;
                const uint32_t va = kbase + 16384 + vrow * 128
                                  + (((2 * jdp + v_cb) ^ sw) << 4);
                ldsm4t(vh4, va);
                ldsm4t(vl4, va + 8192);
                mma16816(oacc[2 * jdp],     ph, &vh4[0]);
                mma16816(oacc[2 * jdp],     ph, &vl4[0]);
                mma16816(oacc[2 * jdp],     pl, &vh4[0]);
                mma16816(oacc[2 * jdp + 1], ph, &vh4[2]);
                mma16816(oacc[2 * jdp + 1], ph, &vl4[2]);
                mma16816(oacc[2 * jdp + 1], pl, &vh4[2]);
            }
        }
        __syncthreads();
    }

    // ---- epilogue: normalize, split to bf16 ctx [b][q][h*64+d] ----
    const float inv0 = 1.0f / l0r, inv1 = 1.0f / l1r;
    const int b_ = bh >> 4, h_ = bh & 15;
    const int q_g = q0 + wid * 16 + g;
    const size_t base0 = ((size_t)(b_ * SQL + q_g)) * DM + h_ * DH;
    const size_t base1 = base0 + (size_t)8 * DM;
#pragma unroll
    for (int jd = 0; jd < 8; jd++) {
        const int dcol = jd * 8 + 2 * tg;
        uint32_t h2, l2;
        split2(oacc[jd][0] * inv0, oacc[jd][1] * inv0, h2, l2);
        *(uint32_t*)(Ch + base0 + dcol) = h2;
        *(uint32_t*)(Cl + base0 + dcol) = l2;
        split2(oacc[jd][2] * inv1, oacc[jd][3] * inv1, h2, l2);
        *(uint32_t*)(Ch + base1 + dcol) = h2;
        *(uint32_t*)(Cl + base1 + dcol) = l2;
    }
}

// ---------------------------------------------------------------------------
extern "C" void kernel_launch(void* const* d_in, const int* in_sizes, int n_in,
                              void* d_out, int out_size)
{
    const float* x1 = (const float*)d_in[0];
    const float* x2 = (const float*)d_in[1];
    const float* Wq = (const float*)d_in[2];
    const float* bq = (const float*)d_in[3];
    const float* Wk = (const float*)d_in[4];
    const float* bk = (const float*)d_in[5];
    const float* Wv = (const float*)d_in[6];
    const float* bv = (const float*)d_in[7];
    const float* Wo = (const float*)d_in[8];
    const float* bo = (const float*)d_in[9];
    float* out = (float*)d_out;

    bf16 *Qh, *Ql, *Kh, *Kl, *Vh, *Vl, *Ah, *Al, *Bh, *Bl;
    bf16 *Wqh, *Wql, *Wkh, *Wkl, *Wvh, *Wvl, *Woh, *Wol;
    cudaGetSymbolAddress((void**)&Qh, g_Qh);  cudaGetSymbolAddress((void**)&Ql, g_Ql);
    cudaGetSymbolAddress((void**)&Kh, g_Kh);  cudaGetSymbolAddress((void**)&Kl, g_Kl);
    cudaGetSymbolAddress((void**)&Vh, g_Vh);  cudaGetSymbolAddress((void**)&Vl, g_Vl);
    cudaGetSymbolAddress((void**)&Ah, g_Ah);  cudaGetSymbolAddress((void**)&Al, g_Al);
    cudaGetSymbolAddress((void**)&Bh, g_Bh);  cudaGetSymbolAddress((void**)&Bl, g_Bl);
    cudaGetSymbolAddress((void**)&Wqh, g_Wqh); cudaGetSymbolAddress((void**)&Wql, g_Wql);
    cudaGetSymbolAddress((void**)&Wkh, g_Wkh); cudaGetSymbolAddress((void**)&Wkl, g_Wkl);
    cudaGetSymbolAddress((void**)&Wvh, g_Wvh); cudaGetSymbolAddress((void**)&Wvl, g_Wvl);
    cudaGetSymbolAddress((void**)&Woh, g_Woh); cudaGetSymbolAddress((void**)&Wol, g_Wol);

    cudaFuncSetAttribute(attn_mma,
                         cudaFuncAttributeMaxDynamicSharedMemorySize, A_SMEM);
    cudaFuncSetAttribute(gemm_mma,
                         cudaFuncAttributeMaxDynamicSharedMemorySize, 2 * GSTG);

    const int half_blocks = (ROWS * DM / 4) / 256;    // 4096
    const float qscale = 0.125f * 1.4426950408889634f;

    // activation splits (x1 -> Ah/Al, x2 -> Bh/Bl) in one launch
    convA_kernel<<<2 * half_blocks, 256>>>(x1, Ah, Al, x2, Bh, Bl, half_blocks);
    // all 4 weight transposes+splits in one launch
    {
        WArgs wa;
        wa.W[0] = Wq; wa.hi[0] = Wqh; wa.lo[0] = Wql;
        wa.W[1] = Wk; wa.hi[1] = Wkh; wa.lo[1] = Wkl;
        wa.W[2] = Wv; wa.hi[2] = Wvh; wa.lo[2] = Wvl;
        wa.W[3] = Wo; wa.hi[3] = Woh; wa.lo[3] = Wol;
        convW_kernel<<<dim3(DM/32, DM/32, 4), dim3(32, 32)>>>(wa);
    }

    // fused QKV projections
    {
        GArgs ga;
        ga.Ah[0] = Ah; ga.Al[0] = Al; ga.Wh[0] = Wqh; ga.Wl[0] = Wql;
        ga.bias[0] = bq; ga.oh[0] = Qh; ga.ol[0] = Ql; ga.of[0] = 0; ga.scale[0] = qscale;
        ga.Ah[1] = Bh; ga.Al[1] = Bl; ga.Wh[1] = Wkh; ga.Wl[1] = Wkl;
        ga.bias[1] = bk; ga.oh[1] = Kh; ga.ol[1] = Kl; ga.of[1] = 0; ga.scale[1] = 1.0f;
        ga.Ah[2] = Bh; ga.Al[2] = Bl; ga.Wh[2] = Wvh; ga.Wl[2] = Wvl;
        ga.bias[2] = bv; ga.oh[2] = Vh; ga.ol[2] = Vl; ga.of[2] = 0; ga.scale[2] = 1.0f;
        gemm_mma<<<dim3(DM/128, ROWS/128, 3), 256, 2 * GSTG>>>(ga);
    }

    // attention -> ctx split (overwrites Ah/Al)
    attn_mma<<<dim3(SQL/64, BH), 128, A_SMEM>>>(Qh, Ql, Kh, Kl, Vh, Vl, Ah, Al);

    // out = ctx @ Wo + bo (fp32)
    {
        GArgs ga;
        ga.Ah[0] = Ah; ga.Al[0] = Al; ga.Wh[0] = Woh; ga.Wl[0] = Wol;
        ga.bias[0] = bo; ga.oh[0] = 0; ga.ol[0] = 0; ga.of[0] = out; ga.scale[0] = 1.0f;
        gemm_mma<<<dim3(DM/128, ROWS/128, 1), 256, 2 * GSTG>>>(ga);
    }
}

// round 6
// speedup vs baseline: 2.8493x; 1.0718x over previous
#include <cuda_runtime.h>
#include <cuda_bf16.h>
#include <math.h>
#include <stdint.h>

#define BB   2
#define SQL  2048
#define DM   1024
#define NH   16
#define DH   64
#define BH   32
#define ROWS 4096

typedef __nv_bfloat16 bf16;

// ---------------- scratch (__device__ globals) -----------------------------
__device__ bf16 g_Qh[BH * SQL * DH];
__device__ bf16 g_Ql[BH * SQL * DH];
__device__ bf16 g_Kh[BH * SQL * DH];
__device__ bf16 g_Kl[BH * SQL * DH];
__device__ bf16 g_Vh[BH * SQL * DH];
__device__ bf16 g_Vl[BH * SQL * DH];
__device__ bf16 g_Ah[ROWS * DM];   // x1 split; later ctx split
__device__ bf16 g_Al[ROWS * DM];
__device__ bf16 g_Bh[ROWS * DM];   // x2 split
__device__ bf16 g_Bl[ROWS * DM];
__device__ bf16 g_Wqh[DM * DM], g_Wql[DM * DM];
__device__ bf16 g_Wkh[DM * DM], g_Wkl[DM * DM];
__device__ bf16 g_Wvh[DM * DM], g_Wvl[DM * DM];
__device__ bf16 g_Woh[DM * DM], g_Wol[DM * DM];

// ---------------- helpers --------------------------------------------------
__device__ __forceinline__ uint32_t smem_to_u32(const void* p) {
    uint32_t a;
    asm("{ .reg .u64 t; cvta.to.shared.u64 t, %1; cvt.u32.u64 %0, t; }"
        : "=r"(a) : "l"(p));
    return a;
}
__device__ __forceinline__ void ldsm4(uint32_t* r, uint32_t a) {
    asm volatile("ldmatrix.sync.aligned.m8n8.x4.shared.b16 {%0,%1,%2,%3}, [%4];"
        : "=r"(r[0]), "=r"(r[1]), "=r"(r[2]), "=r"(r[3]) : "r"(a));
}
__device__ __forceinline__ void ldsm4t(uint32_t* r, uint32_t a) {
    asm volatile("ldmatrix.sync.aligned.m8n8.x4.trans.shared.b16 {%0,%1,%2,%3}, [%4];"
        : "=r"(r[0]), "=r"(r[1]), "=r"(r[2]), "=r"(r[3]) : "r"(a));
}
__device__ __forceinline__ void mma16816(float* c, const uint32_t* a, const uint32_t* b) {
    asm volatile("mma.sync.aligned.m16n8k16.row.col.f32.bf16.bf16.f32 "
        "{%0,%1,%2,%3}, {%4,%5,%6,%7}, {%8,%9}, {%0,%1,%2,%3};"
        : "+f"(c[0]), "+f"(c[1]), "+f"(c[2]), "+f"(c[3])
        : "r"(a[0]), "r"(a[1]), "r"(a[2]), "r"(a[3]), "r"(b[0]), "r"(b[1]));
}
__device__ __forceinline__ void split2(float v0, float v1, uint32_t& hi2, uint32_t& lo2) {
    __nv_bfloat16 b0 = __float2bfloat16_rn(v0), b1 = __float2bfloat16_rn(v1);
    union { __nv_bfloat162 v; uint32_t u; } p;
    p.v.x = b0; p.v.y = b1; hi2 = p.u;
    p.v.x = __float2bfloat16_rn(v0 - __bfloat162float(b0));
    p.v.y = __float2bfloat16_rn(v1 - __bfloat162float(b1));
    lo2 = p.u;
}
__device__ __forceinline__ float ex2(float x) {
    float y; asm("ex2.approx.f32 %0, %1;" : "=f"(y) : "f"(x)); return y;
}
#define CP16(dst, src) \
    asm volatile("cp.async.cg.shared.global [%0], [%1], 16;" :: "r"(dst), "l"(src))
#define CP_COMMIT() asm volatile("cp.async.commit_group;" ::: "memory")
#define CP_WAIT(n)  asm volatile("cp.async.wait_group %0;" :: "n"(n) : "memory")

// ---------------- conversion kernels ---------------------------------------
__global__ __launch_bounds__(256)
void convA_kernel(const float* __restrict__ x1, bf16* __restrict__ hi1,
                  bf16* __restrict__ lo1,
                  const float* __restrict__ x2, bf16* __restrict__ hi2v,
                  bf16* __restrict__ lo2v, int half)
{
    int bi = blockIdx.x;
    const float* x; bf16 *hi, *lo;
    if (bi < half) { x = x1; hi = hi1; lo = lo1; }
    else           { x = x2; hi = hi2v; lo = lo2v; bi -= half; }
    int i = bi * 256 + threadIdx.x;
    float4 v = ((const float4*)x)[i];
    uint32_t h0, l0, h1, l1;
    split2(v.x, v.y, h0, l0);
    split2(v.z, v.w, h1, l1);
    ((uint32_t*)hi)[2 * i] = h0; ((uint32_t*)hi)[2 * i + 1] = h1;
    ((uint32_t*)lo)[2 * i] = l0; ((uint32_t*)lo)[2 * i + 1] = l1;
}

struct WArgs { const float* W[4]; bf16* hi[4]; bf16* lo[4]; };
__global__ __launch_bounds__(1024)
void convW_kernel(WArgs a)
{
    const int z = blockIdx.z;
    const float* __restrict__ W = a.W[z];
    bf16* __restrict__ hi = a.hi[z];
    bf16* __restrict__ lo = a.lo[z];
    __shared__ float tile[32][33];
    int tx = threadIdx.x, ty = threadIdx.y;
    int k = blockIdx.y * 32 + ty;
    int n = blockIdx.x * 32 + tx;
    tile[ty][tx] = W[(size_t)k * DM + n];
    __syncthreads();
    int nn = blockIdx.x * 32 + ty;
    int kk = blockIdx.y * 32 + tx;
    float v = tile[tx][ty];
    __nv_bfloat16 h = __float2bfloat16_rn(v);
    hi[(size_t)nn * DM + kk] = h;
    lo[(size_t)nn * DM + kk] = __float2bfloat16_rn(v - __bfloat162float(h));
}

// ---------------- split-bf16 GEMM: 64x128 tile, 128 thr, 2 CTA/SM ----------
// C[m][n] = sum_k (Ah+Al)[m][k] * (Wh+Wl)[n][k]; then (C + bias) * scale.
// smem stage: Ah 64x80, Al 64x80, Bh 128x80, Bl 128x80 = 30720 B; 2 stages.
struct GArgs {
    const bf16* Ah[3]; const bf16* Al[3];
    const bf16* Wh[3]; const bf16* Wl[3];
    const float* bias[3];
    bf16* oh[3]; bf16* ol[3];
    float* of[3];
    float scale[3];
};
#define GSTG   30720
#define G_OFAL 5120
#define G_OFBH 10240
#define G_OFBL 20480
__global__ __launch_bounds__(128, 2)
void gemm_mma(GArgs ar)
{
    extern __shared__ __align__(16) char dsm[];
    const int z = blockIdx.z;
    const bf16* __restrict__ Ah = ar.Ah[z];
    const bf16* __restrict__ Al = ar.Al[z];
    const bf16* __restrict__ Bh = ar.Wh[z];
    const bf16* __restrict__ Bl = ar.Wl[z];
    const float* __restrict__ bias = ar.bias[z];
    const float scale = ar.scale[z];

    const uint32_t sb0 = smem_to_u32(dsm);
    const int t = threadIdx.x, L = t & 31, wid = t >> 5;
    const int wm = wid & 1, wn = wid >> 1;          // 2x2 warp grid
    const int m0 = blockIdx.y * 64, n0 = blockIdx.x * 128;

    const int r0 = t >> 2, c0 = t & 3;               // 32 rows x 4 chunks
    auto copy_stage = [&](int st, int k0) {
        const uint32_t d0 = sb0 + st * GSTG + r0 * 80 + c0 * 16;
        const char* gAh = (const char*)(Ah + (size_t)(m0 + r0) * DM + k0 + c0 * 8);
        const char* gAl = (const char*)(Al + (size_t)(m0 + r0) * DM + k0 + c0 * 8);
        const char* gBh = (const char*)(Bh + (size_t)(n0 + r0) * DM + k0 + c0 * 8);
        const char* gBl = (const char*)(Bl + (size_t)(n0 + r0) * DM + k0 + c0 * 8);
        // A: 64 rows (r0, r0+32)
        CP16(d0,                      gAh);
        CP16(d0 + 32 * 80,            gAh + 32 * DM * 2);
        CP16(d0 + G_OFAL,             gAl);
        CP16(d0 + G_OFAL + 32 * 80,   gAl + 32 * DM * 2);
        // B: 128 rows (r0, +32, +64, +96)
        CP16(d0 + G_OFBH,             gBh);
        CP16(d0 + G_OFBH + 32 * 80,   gBh + 32 * DM * 2);
        CP16(d0 + G_OFBH + 64 * 80,   gBh + 64 * DM * 2);
        CP16(d0 + G_OFBH + 96 * 80,   gBh + 96 * DM * 2);
        CP16(d0 + G_OFBL,             gBl);
        CP16(d0 + G_OFBL + 32 * 80,   gBl + 32 * DM * 2);
        CP16(d0 + G_OFBL + 64 * 80,   gBl + 64 * DM * 2);
        CP16(d0 + G_OFBL + 96 * 80,   gBl + 96 * DM * 2);
    };

    float acc[2][8][4];
#pragma unroll
    for (int a = 0; a < 2; a++)
#pragma unroll
        for (int b = 0; b < 8; b++)
#pragma unroll
            for (int c = 0; c < 4; c++) acc[a][b][c] = 0.0f;

    const int a_row_off = ((L >> 3) & 1) * 8 + (L & 7);
    const int a_ch = (L >> 4);
    const int b_row_off = ((L >> 4) & 1) * 8 + (L & 7);
    const int b_ch = ((L >> 3) & 1);

    copy_stage(0, 0);
    CP_COMMIT();

    for (int kt = 0; kt < 32; kt++) {
        const int cur = kt & 1;
        if (kt < 31) { copy_stage(1 - cur, (kt + 1) * 32); CP_COMMIT(); CP_WAIT(1); }
        else CP_WAIT(0);
        __syncthreads();
        const uint32_t sb = sb0 + cur * GSTG;
#pragma unroll
        for (int ks = 0; ks < 2; ks++) {
            uint32_t aH[2][4], aL[2][4], bHf[4][4], bLf[4][4];
            const int ach = (2 * ks + a_ch) * 16;
#pragma unroll
            for (int mt = 0; mt < 2; mt++) {
                const uint32_t ad = sb + (wm * 32 + mt * 16 + a_row_off) * 80 + ach;
                ldsm4(aH[mt], ad);
                ldsm4(aL[mt], ad + G_OFAL);
            }
            const int bch = (2 * ks + b_ch) * 16;
#pragma unroll
            for (int np = 0; np < 4; np++) {
                const uint32_t bd = sb + G_OFBH + (wn * 64 + np * 16 + b_row_off) * 80 + bch;
                ldsm4(bHf[np], bd);
                ldsm4(bLf[np], bd + G_OFBH);   // Bl is 10240 after Bh
            }
#pragma unroll
            for (int mt = 0; mt < 2; mt++)
#pragma unroll
                for (int nt = 0; nt < 8; nt++) {
                    const uint32_t* bh_ = &bHf[nt >> 1][(nt & 1) * 2];
                    const uint32_t* bl_ = &bLf[nt >> 1][(nt & 1) * 2];
                    mma16816(acc[mt][nt], aH[mt], bh_);
                    mma16816(acc[mt][nt], aH[mt], bl_);
                    mma16816(acc[mt][nt], aL[mt], bh_);
                }
        }
        __syncthreads();
    }

    bf16* __restrict__ outH = ar.oh[z];
    bf16* __restrict__ outL = ar.ol[z];
    float* __restrict__ outF = ar.of[z];
    const int g = L >> 2, tg = L & 3;
#pragma unroll
    for (int mt = 0; mt < 2; mt++) {
#pragma unroll
        for (int nt = 0; nt < 8; nt++) {
            const int mrow = m0 + wm * 32 + mt * 16 + g;
            const int ncol = n0 + wn * 64 + nt * 8 + 2 * tg;
            const float b0v = bias[ncol], b1v = bias[ncol + 1];
            const float v00 = (acc[mt][nt][0] + b0v) * scale;
            const float v01 = (acc[mt][nt][1] + b1v) * scale;
            const float v10 = (acc[mt][nt][2] + b0v) * scale;
            const float v11 = (acc[mt][nt][3] + b1v) * scale;
            if (outF) {
                *(float2*)(outF + (size_t)mrow * DM + ncol) = make_float2(v00, v01);
                *(float2*)(outF + (size_t)(mrow + 8) * DM + ncol) = make_float2(v10, v11);
            } else {
                const int b_ = mrow >> 11, s_ = mrow & 2047;
                const int h_ = ncol >> 6, d_ = ncol & 63;
                const size_t oi = ((size_t)(b_ * NH + h_) * SQL + s_) * DH + d_;
                uint32_t h2, l2;
                split2(v00, v01, h2, l2);
                *(uint32_t*)(outH + oi) = h2;
                *(uint32_t*)(outL + oi) = l2;
                split2(v10, v11, h2, l2);
                *(uint32_t*)(outH + oi + 8 * DH) = h2;
                *(uint32_t*)(outL + oi + 8 * DH) = l2;
            }
        }
    }
}

// ---------------- flash attention: q-tile 64, k-tile 64, 128 thr, 2 CTA/SM -
#define A_SMEM  81920
#define ASTG_B  16384
#define ASTG_S  32768
__global__ __launch_bounds__(128, 2)
void attn_mma(const bf16* __restrict__ Qh, const bf16* __restrict__ Ql,
              const bf16* __restrict__ Kh, const bf16* __restrict__ Kl,
              const bf16* __restrict__ Vh, const bf16* __restrict__ Vl,
              bf16* __restrict__ Ch, bf16* __restrict__ Cl)
{
    extern __shared__ __align__(16) char sm_[];
    const uint32_t sb = smem_to_u32(sm_);
    const int t = threadIdx.x, L = t & 31, wid = t >> 5;
    const int bh = blockIdx.y, q0 = blockIdx.x * 64;
    const int g = L >> 2, tg = L & 3;

    const int a_row = wid * 16 + ((L >> 3) & 1) * 8 + (L & 7);
    const int a_cb  = (L >> 4);
    const int k_row_off = ((L >> 4) & 1) * 8 + (L & 7);
    const int k_cb  = ((L >> 3) & 1);
    const int v_row_off = ((L >> 3) & 1) * 8 + (L & 7);
    const int v_cb  = (L >> 4);
    const int sw    = L & 7;

    auto copy_kv = [&](int st, int kb) {
        const uint32_t base = sb + ASTG_B + st * ASTG_S;
        const size_t goff = ((size_t)bh * SQL + kb * 64) * DH;
        const char* kh = (const char*)(Kh + goff);
        const char* kl = (const char*)(Kl + goff);
        const char* vh = (const char*)(Vh + goff);
        const char* vl = (const char*)(Vl + goff);
#pragma unroll
        for (int i = 0; i < 4; i++) {
            const int u = t + i * 128, r = u >> 3, c = u & 7;
            const uint32_t so = r * 128 + ((c ^ (r & 7)) << 4);
            const int go = r * 128 + c * 16;
            CP16(base + so,         kh + go);
            CP16(base + 8192 + so,  kl + go);
            CP16(base + 16384 + so, vh + go);
            CP16(base + 24576 + so, vl + go);
        }
    };

    copy_kv(0, 0);
    {
        const char* qh = (const char*)(Qh + ((size_t)bh * SQL + q0) * DH);
        const char* ql = (const char*)(Ql + ((size_t)bh * SQL + q0) * DH);
#pragma unroll
        for (int i = 0; i < 4; i++) {
            const int u = t + i * 128, r = u >> 3, c = u & 7;
            const uint32_t so = r * 128 + ((c ^ (r & 7)) << 4);
            const int go = r * 128 + c * 16;
            CP16(sb + so,        qh + go);
            CP16(sb + 8192 + so, ql + go);
        }
    }
    CP_COMMIT();
    CP_WAIT(0);
    __syncthreads();

    uint32_t qH[4][4], qL[4][4];
#pragma unroll
    for (int ks = 0; ks < 4; ks++) {
        const uint32_t qa = sb + a_row * 128 + (((2 * ks + a_cb) ^ sw) << 4);
        ldsm4(qH[ks], qa);
        ldsm4(qL[ks], qa + 8192);
    }

    float oacc[8][4];
#pragma unroll
    for (int a = 0; a < 8; a++)
#pragma unroll
        for (int b = 0; b < 4; b++) oacc[a][b] = 0.0f;
    float m0r = -1e30f, m1r = -1e30f, l0r = 0.0f, l1r = 0.0f;

    for (int kb = 0; kb < 32; kb++) {
        const int cur = kb & 1;
        if (kb < 31) { copy_kv(1 - cur, kb + 1); CP_COMMIT(); CP_WAIT(1); }
        else CP_WAIT(0);
        __syncthreads();
        const uint32_t kbase = sb + ASTG_B + cur * ASTG_S;

        // ---- S = Q @ K^T (exp2 domain; 0.125*log2e folded into Q) ----
        float sacc[8][4];
#pragma unroll
        for (int j = 0; j < 8; j++)
#pragma unroll
            for (int c = 0; c < 4; c++) sacc[j][c] = 0.0f;

#pragma unroll
        for (int ks = 0; ks < 4; ks++) {
#pragma unroll
            for (int jp = 0; jp < 4; jp++) {
                uint32_t kh4[4], kl4[4];
                const int krow = jp * 16 + k_row_off;
                const uint32_t ka = kbase + krow * 128 + (((2 * ks + k_cb) ^ sw) << 4);
                ldsm4(kh4, ka);
                ldsm4(kl4, ka + 8192);
                mma16816(sacc[2 * jp],     qH[ks], &kh4[0]);
                mma16816(sacc[2 * jp],     qH[ks], &kl4[0]);
                mma16816(sacc[2 * jp],     qL[ks], &kh4[0]);
                mma16816(sacc[2 * jp + 1], qH[ks], &kh4[2]);
                mma16816(sacc[2 * jp + 1], qH[ks], &kl4[2]);
                mma16816(sacc[2 * jp + 1], qL[ks], &kh4[2]);
            }
        }

        // ---- online softmax ----
        float rx0 = -1e30f, rx1 = -1e30f;
#pragma unroll
        for (int j = 0; j < 8; j++) {
            rx0 = fmaxf(rx0, fmaxf(sacc[j][0], sacc[j][1]));
            rx1 = fmaxf(rx1, fmaxf(sacc[j][2], sacc[j][3]));
        }
        rx0 = fmaxf(rx0, __shfl_xor_sync(0xffffffffu, rx0, 1));
        rx0 = fmaxf(rx0, __shfl_xor_sync(0xffffffffu, rx0, 2));
        rx1 = fmaxf(rx1, __shfl_xor_sync(0xffffffffu, rx1, 1));
        rx1 = fmaxf(rx1, __shfl_xor_sync(0xffffffffu, rx1, 2));
        const float mn0 = fmaxf(m0r, rx0), mn1 = fmaxf(m1r, rx1);
        const float al0 = ex2(m0r - mn0), al1 = ex2(m1r - mn1);
        m0r = mn0; m1r = mn1;

        float rs0 = 0.0f, rs1 = 0.0f;
#pragma unroll
        for (int j = 0; j < 8; j++) {
            const float p0 = ex2(sacc[j][0] - mn0);
            const float p1 = ex2(sacc[j][1] - mn0);
            const float p2 = ex2(sacc[j][2] - mn1);
            const float p3 = ex2(sacc[j][3] - mn1);
            sacc[j][0] = p0; sacc[j][1] = p1; sacc[j][2] = p2; sacc[j][3] = p3;
            rs0 += p0 + p1; rs1 += p2 + p3;
        }
        rs0 += __shfl_xor_sync(0xffffffffu, rs0, 1);
        rs0 += __shfl_xor_sync(0xffffffffu, rs0, 2);
        rs1 += __shfl_xor_sync(0xffffffffu, rs1, 1);
        rs1 += __shfl_xor_sync(0xffffffffu, rs1, 2);
        l0r = l0r * al0 + rs0;
        l1r = l1r * al1 + rs1;
#pragma unroll
        for (int jd = 0; jd < 8; jd++) {
            oacc[jd][0] *= al0; oacc[jd][1] *= al0;
            oacc[jd][2] *= al1; oacc[jd][3] *= al1;
        }

        // ---- O += P @ V (split P on the fly) ----
#pragma unroll
        for (int ks2 = 0; ks2 < 4; ks2++) {
            uint32_t ph[4], pl[4];
            split2(sacc[2 * ks2][0],     sacc[2 * ks2][1],     ph[0], pl[0]);
            split2(sacc[2 * ks2][2],     sacc[2 * ks2][3],     ph[1], pl[1]);
            split2(sacc[2 * ks2 + 1][0], sacc[2 * ks2 + 1][1], ph[2], pl[2]);
            split2(sacc[2 * ks2 + 1][2], sacc[2 * ks2 + 1][3], ph[3], pl[3]);
#pragma unroll
            for (int jdp = 0; jdp < 4; jdp++) {
                uint32_t vh4[4], vl4[4];
                const int vrow = ks2 * 16 + v_row_off;
                const uint32_t va = kbase + 16384 + vrow * 128
                                  + (((2 * jdp + v_cb) ^ sw) << 4);
                ldsm4t(vh4, va);
                ldsm4t(vl4, va + 8192);
                mma16816(oacc[2 * jdp],     ph, &vh4[0]);
                mma16816(oacc[2 * jdp],     ph, &vl4[0]);
                mma16816(oacc[2 * jdp],     pl, &vh4[0]);
                mma16816(oacc[2 * jdp + 1], ph, &vh4[2]);
                mma16816(oacc[2 * jdp + 1], ph, &vl4[2]);
                mma16816(oacc[2 * jdp + 1], pl, &vh4[2]);
            }
        }
        __syncthreads();
    }

    // ---- epilogue ----
    const float inv0 = 1.0f / l0r, inv1 = 1.0f / l1r;
    const int b_ = bh >> 4, h_ = bh & 15;
    const int q_g = q0 + wid * 16 + g;
    const size_t base0 = ((size_t)(b_ * SQL + q_g)) * DM + h_ * DH;
    const size_t base1 = base0 + (size_t)8 * DM;
#pragma unroll
    for (int jd = 0; jd < 8; jd++) {
        const int dcol = jd * 8 + 2 * tg;
        uint32_t h2, l2;
        split2(oacc[jd][0] * inv0, oacc[jd][1] * inv0, h2, l2);
        *(uint32_t*)(Ch + base0 + dcol) = h2;
        *(uint32_t*)(Cl + base0 + dcol) = l2;
        split2(oacc[jd][2] * inv1, oacc[jd][3] * inv1, h2, l2);
        *(uint32_t*)(Ch + base1 + dcol) = h2;
        *(uint32_t*)(Cl + base1 + dcol) = l2;
    }
}

// ---------------------------------------------------------------------------
extern "C" void kernel_launch(void* const* d_in, const int* in_sizes, int n_in,
                              void* d_out, int out_size)
{
    const float* x1 = (const float*)d_in[0];
    const float* x2 = (const float*)d_in[1];
    const float* Wq = (const float*)d_in[2];
    const float* bq = (const float*)d_in[3];
    const float* Wk = (const float*)d_in[4];
    const float* bk = (const float*)d_in[5];
    const float* Wv = (const float*)d_in[6];
    const float* bv = (const float*)d_in[7];
    const float* Wo = (const float*)d_in[8];
    const float* bo = (const float*)d_in[9];
    float* out = (float*)d_out;

    bf16 *Qh, *Ql, *Kh, *Kl, *Vh, *Vl, *Ah, *Al, *Bh, *Bl;
    bf16 *Wqh, *Wql, *Wkh, *Wkl, *Wvh, *Wvl, *Woh, *Wol;
    cudaGetSymbolAddress((void**)&Qh, g_Qh);  cudaGetSymbolAddress((void**)&Ql, g_Ql);
    cudaGetSymbolAddress((void**)&Kh, g_Kh);  cudaGetSymbolAddress((void**)&Kl, g_Kl);
    cudaGetSymbolAddress((void**)&Vh, g_Vh);  cudaGetSymbolAddress((void**)&Vl, g_Vl);
    cudaGetSymbolAddress((void**)&Ah, g_Ah);  cudaGetSymbolAddress((void**)&Al, g_Al);
    cudaGetSymbolAddress((void**)&Bh, g_Bh);  cudaGetSymbolAddress((void**)&Bl, g_Bl);
    cudaGetSymbolAddress((void**)&Wqh, g_Wqh); cudaGetSymbolAddress((void**)&Wql, g_Wql);
    cudaGetSymbolAddress((void**)&Wkh, g_Wkh); cudaGetSymbolAddress((void**)&Wkl, g_Wkl);
    cudaGetSymbolAddress((void**)&Wvh, g_Wvh); cudaGetSymbolAddress((void**)&Wvl, g_Wvl);
    cudaGetSymbolAddress((void**)&Woh, g_Woh); cudaGetSymbolAddress((void**)&Wol, g_Wol);

    cudaFuncSetAttribute(attn_mma,
                         cudaFuncAttributeMaxDynamicSharedMemorySize, A_SMEM);
    cudaFuncSetAttribute(gemm_mma,
                         cudaFuncAttributeMaxDynamicSharedMemorySize, 2 * GSTG);

    const int half_blocks = (ROWS * DM / 4) / 256;    // 4096
    const float qscale = 0.125f * 1.4426950408889634f;

    convA_kernel<<<2 * half_blocks, 256>>>(x1, Ah, Al, x2, Bh, Bl, half_blocks);
    {
        WArgs wa;
        wa.W[0] = Wq; wa.hi[0] = Wqh; wa.lo[0] = Wql;
        wa.W[1] = Wk; wa.hi[1] = Wkh; wa.lo[1] = Wkl;
        wa.W[2] = Wv; wa.hi[2] = Wvh; wa.lo[2] = Wvl;
        wa.W[3] = Wo; wa.hi[3] = Woh; wa.lo[3] = Wol;
        convW_kernel<<<dim3(DM/32, DM/32, 4), dim3(32, 32)>>>(wa);
    }

    // fused QKV projections (tile 64x128 -> grid (8, 64, 3))
    {
        GArgs ga;
        ga.Ah[0] = Ah; ga.Al[0] = Al; ga.Wh[0] = Wqh; ga.Wl[0] = Wql;
        ga.bias[0] = bq; ga.oh[0] = Qh; ga.ol[0] = Ql; ga.of[0] = 0; ga.scale[0] = qscale;
        ga.Ah[1] = Bh; ga.Al[1] = Bl; ga.Wh[1] = Wkh; ga.Wl[1] = Wkl;
        ga.bias[1] = bk; ga.oh[1] = Kh; ga.ol[1] = Kl; ga.of[1] = 0; ga.scale[1] = 1.0f;
        ga.Ah[2] = Bh; ga.Al[2] = Bl; ga.Wh[2] = Wvh; ga.Wl[2] = Wvl;
        ga.bias[2] = bv; ga.oh[2] = Vh; ga.ol[2] = Vl; ga.of[2] = 0; ga.scale[2] = 1.0f;
        gemm_mma<<<dim3(DM/128, ROWS/64, 3), 128, 2 * GSTG>>>(ga);
    }

    // attention -> ctx split (overwrites Ah/Al)
    attn_mma<<<dim3(SQL/64, BH), 128, A_SMEM>>>(Qh, Ql, Kh, Kl, Vh, Vl, Ah, Al);

    // out = ctx @ Wo + bo (fp32)
    {
        GArgs ga;
        ga.Ah[0] = Ah; ga.Al[0] = Al; ga.Wh[0] = Woh; ga.Wl[0] = Wol;
        ga.bias[0] = bo; ga.oh[0] = 0; ga.ol[0] = 0; ga.of[0] = out; ga.scale[0] = 1.0f;
        gemm_mma<<<dim3(DM/128, ROWS/64, 1), 128, 2 * GSTG>>>(ga);
    }
}

// round 7
// speedup vs baseline: 3.3036x; 1.1595x over previous
#include <cuda_runtime.h>
#include <cuda_bf16.h>
#include <math.h>
#include <stdint.h>

#define BB   2
#define SQL  2048
#define DM   1024
#define NH   16
#define DH   64
#define BH   32
#define ROWS 4096

typedef __nv_bfloat16 bf16;

// ---------------- scratch (__device__ globals) -----------------------------
__device__ bf16 g_Qh[BH * SQL * DH];
__device__ bf16 g_Ql[BH * SQL * DH];
__device__ bf16 g_Kh[BH * SQL * DH];
__device__ bf16 g_Kl[BH * SQL * DH];
__device__ bf16 g_Vh[BH * SQL * DH];
__device__ bf16 g_Vl[BH * SQL * DH];
__device__ bf16 g_Ah[ROWS * DM];   // x1 split; later ctx split
__device__ bf16 g_Al[ROWS * DM];
__device__ bf16 g_Bh[ROWS * DM];   // x2 split
__device__ bf16 g_Bl[ROWS * DM];
__device__ bf16 g_Wqh[DM * DM], g_Wql[DM * DM];   // untransposed [k][n]
__device__ bf16 g_Wkh[DM * DM], g_Wkl[DM * DM];
__device__ bf16 g_Wvh[DM * DM], g_Wvl[DM * DM];
__device__ bf16 g_Woh[DM * DM], g_Wol[DM * DM];

// ---------------- helpers --------------------------------------------------
__device__ __forceinline__ uint32_t smem_to_u32(const void* p) {
    uint32_t a;
    asm("{ .reg .u64 t; cvta.to.shared.u64 t, %1; cvt.u32.u64 %0, t; }"
        : "=r"(a) : "l"(p));
    return a;
}
__device__ __forceinline__ void ldsm4(uint32_t* r, uint32_t a) {
    asm volatile("ldmatrix.sync.aligned.m8n8.x4.shared.b16 {%0,%1,%2,%3}, [%4];"
        : "=r"(r[0]), "=r"(r[1]), "=r"(r[2]), "=r"(r[3]) : "r"(a));
}
__device__ __forceinline__ void ldsm4t(uint32_t* r, uint32_t a) {
    asm volatile("ldmatrix.sync.aligned.m8n8.x4.trans.shared.b16 {%0,%1,%2,%3}, [%4];"
        : "=r"(r[0]), "=r"(r[1]), "=r"(r[2]), "=r"(r[3]) : "r"(a));
}
__device__ __forceinline__ void mma16816(float* c, const uint32_t* a, const uint32_t* b) {
    asm volatile("mma.sync.aligned.m16n8k16.row.col.f32.bf16.bf16.f32 "
        "{%0,%1,%2,%3}, {%4,%5,%6,%7}, {%8,%9}, {%0,%1,%2,%3};"
        : "+f"(c[0]), "+f"(c[1]), "+f"(c[2]), "+f"(c[3])
        : "r"(a[0]), "r"(a[1]), "r"(a[2]), "r"(a[3]), "r"(b[0]), "r"(b[1]));
}
__device__ __forceinline__ void split2(float v0, float v1, uint32_t& hi2, uint32_t& lo2) {
    __nv_bfloat16 b0 = __float2bfloat16_rn(v0), b1 = __float2bfloat16_rn(v1);
    union { __nv_bfloat162 v; uint32_t u; } p;
    p.v.x = b0; p.v.y = b1; hi2 = p.u;
    p.v.x = __float2bfloat16_rn(v0 - __bfloat162float(b0));
    p.v.y = __float2bfloat16_rn(v1 - __bfloat162float(b1));
    lo2 = p.u;
}
__device__ __forceinline__ float ex2(float x) {
    float y; asm("ex2.approx.f32 %0, %1;" : "=f"(y) : "f"(x)); return y;
}
#define CP16(dst, src) \
    asm volatile("cp.async.cg.shared.global [%0], [%1], 16;" :: "r"(dst), "l"(src))
#define CP_COMMIT() asm volatile("cp.async.commit_group;" ::: "memory")
#define CP_WAIT(n)  asm volatile("cp.async.wait_group %0;" :: "n"(n) : "memory")

// ---------------- one split kernel for x1, x2, and the 4 weights -----------
struct SArgs { const float* s[6]; bf16* h[6]; bf16* l[6]; };
__global__ __launch_bounds__(256)
void convS_kernel(SArgs a)
{
    int bi = blockIdx.x, z;
    // x1: 4096 blocks, x2: 4096, each W: 1024
    if (bi < 4096)       { z = 0; }
    else if (bi < 8192)  { z = 1; bi -= 4096; }
    else                 { z = 2 + ((bi - 8192) >> 10); bi = (bi - 8192) & 1023; }
    const float* __restrict__ x = a.s[z];
    bf16* __restrict__ hi = a.h[z];
    bf16* __restrict__ lo = a.l[z];
    int i = bi * 256 + threadIdx.x;
    float4 v = ((const float4*)x)[i];
    uint32_t h0, l0, h1, l1;
    split2(v.x, v.y, h0, l0);
    split2(v.z, v.w, h1, l1);
    ((uint32_t*)hi)[2 * i] = h0; ((uint32_t*)hi)[2 * i + 1] = h1;
    ((uint32_t*)lo)[2 * i] = l0; ((uint32_t*)lo)[2 * i + 1] = l1;
}

// ---------------- split-bf16 GEMM: 64x128 tile, 128 thr, 2 CTA/SM, 3-stage -
// C[m][n] = sum_k (Ah+Al)[m][k] * (Wh+Wl)[k][n]  (W untransposed; B via ldsm4t)
// stage: Ah 64x80B, Al 64x80B, Bh 32x256B, Bl 32x256B  = 26624 B; 3 stages.
struct GArgs {
    const bf16* Ah[3]; const bf16* Al[3];
    const bf16* Wh[3]; const bf16* Wl[3];
    const float* bias[3];
    bf16* oh[3]; bf16* ol[3];
    float* of[3];
    float scale[3];
};
#define GSTG   26624
#define G_OFAL 5120
#define G_OFBH 10240
#define G_OFBL 18432
__global__ __launch_bounds__(128, 2)
void gemm_mma(GArgs ar)
{
    extern __shared__ __align__(16) char dsm[];
    const int z = blockIdx.z;
    const bf16* __restrict__ Ah = ar.Ah[z];
    const bf16* __restrict__ Al = ar.Al[z];
    const bf16* __restrict__ Wh = ar.Wh[z];
    const bf16* __restrict__ Wl = ar.Wl[z];
    const float* __restrict__ bias = ar.bias[z];
    const float scale = ar.scale[z];

    const uint32_t sb0 = smem_to_u32(dsm);
    const int t = threadIdx.x, L = t & 31, wid = t >> 5;
    const int wm = wid & 1, wn = wid >> 1;          // 2x2 warp grid
    const int m0 = blockIdx.y * 64, n0 = blockIdx.x * 128;

    auto copy_stage = [&](int st, int k0) {
        const uint32_t base = sb0 + st * GSTG;
        // A: 64 rows x 4 chunks (16B), 2 per thread
#pragma unroll
        for (int i = 0; i < 2; i++) {
            const int u = t + i * 128, r = u >> 2, c = u & 3;
            const uint32_t d = base + r * 80 + c * 16;
            const size_t gi = (size_t)(m0 + r) * DM + k0 + c * 8;
            CP16(d,          Ah + gi);
            CP16(d + G_OFAL, Al + gi);
        }
        // B (W[k][n]): 32 rows x 16 chunks, swizzle c ^ (r&7), 4 per thread
#pragma unroll
        for (int i = 0; i < 4; i++) {
            const int u = t + i * 128, r = u >> 4, c = u & 15;
            const uint32_t d = base + G_OFBH + r * 256 + (c ^ (r & 7)) * 16;
            const size_t gi = (size_t)(k0 + r) * DM + n0 + c * 8;
            CP16(d,        Wh + gi);
            CP16(d + 8192, Wl + gi);
        }
    };

    float acc[2][8][4];
#pragma unroll
    for (int a = 0; a < 2; a++)
#pragma unroll
        for (int b = 0; b < 8; b++)
#pragma unroll
            for (int c = 0; c < 4; c++) acc[a][b][c] = 0.0f;

    const int a_row_off = ((L >> 3) & 1) * 8 + (L & 7);
    const int a_ch = (L >> 4);
    const int trow = ((L >> 3) & 1) * 8 + (L & 7);   // B trans row pattern
    const int tcb  = (L >> 4);                       // B trans chunk half
    const int sw7  = L & 7;

    copy_stage(0, 0);  CP_COMMIT();
    copy_stage(1, 32); CP_COMMIT();

    for (int kt = 0; kt < 32; kt++) {
        if (kt == 31) CP_WAIT(0); else CP_WAIT(1);
        __syncthreads();
        if (kt < 30) { copy_stage((kt + 2) % 3, (kt + 2) * 32); CP_COMMIT(); }
        const uint32_t sb = sb0 + (kt % 3) * GSTG;
#pragma unroll
        for (int ks = 0; ks < 2; ks++) {
            uint32_t aH[2][4], aL[2][4];
            const int ach = (2 * ks + a_ch) * 16;
#pragma unroll
            for (int mt = 0; mt < 2; mt++) {
                const uint32_t ad = sb + (wm * 32 + mt * 16 + a_row_off) * 80 + ach;
                ldsm4(aH[mt], ad);
                ldsm4(aL[mt], ad + G_OFAL);
            }
            const int krow = ks * 16 + trow;
#pragma unroll
            for (int ns = 0; ns < 4; ns++) {
                uint32_t bTh[4], bTl[4];
                const int ch = 2 * (wn * 4 + ns) + tcb;
                const uint32_t bd = sb + G_OFBH + krow * 256 + ((ch ^ sw7) << 4);
                ldsm4t(bTh, bd);
                ldsm4t(bTl, bd + 8192);
#pragma unroll
                for (int mt = 0; mt < 2; mt++) {
                    mma16816(acc[mt][2 * ns],     aH[mt], &bTh[0]);
                    mma16816(acc[mt][2 * ns],     aH[mt], &bTl[0]);
                    mma16816(acc[mt][2 * ns],     aL[mt], &bTh[0]);
                    mma16816(acc[mt][2 * ns + 1], aH[mt], &bTh[2]);
                    mma16816(acc[mt][2 * ns + 1], aH[mt], &bTl[2]);
                    mma16816(acc[mt][2 * ns + 1], aL[mt], &bTh[2]);
                }
            }
        }
    }

    bf16* __restrict__ outH = ar.oh[z];
    bf16* __restrict__ outL = ar.ol[z];
    float* __restrict__ outF = ar.of[z];
    const int g = L >> 2, tg = L & 3;
#pragma unroll
    for (int mt = 0; mt < 2; mt++) {
#pragma unroll
        for (int nt = 0; nt < 8; nt++) {
            const int mrow = m0 + wm * 32 + mt * 16 + g;
            const int ncol = n0 + wn * 64 + nt * 8 + 2 * tg;
            const float b0v = bias[ncol], b1v = bias[ncol + 1];
            const float v00 = (acc[mt][nt][0] + b0v) * scale;
            const float v01 = (acc[mt][nt][1] + b1v) * scale;
            const float v10 = (acc[mt][nt][2] + b0v) * scale;
            const float v11 = (acc[mt][nt][3] + b1v) * scale;
            if (outF) {
                *(float2*)(outF + (size_t)mrow * DM + ncol) = make_float2(v00, v01);
                *(float2*)(outF + (size_t)(mrow + 8) * DM + ncol) = make_float2(v10, v11);
            } else {
                const int b_ = mrow >> 11, s_ = mrow & 2047;
                const int h_ = ncol >> 6, d_ = ncol & 63;
                const size_t oi = ((size_t)(b_ * NH + h_) * SQL + s_) * DH + d_;
                uint32_t h2, l2;
                split2(v00, v01, h2, l2);
                *(uint32_t*)(outH + oi) = h2;
                *(uint32_t*)(outL + oi) = l2;
                split2(v10, v11, h2, l2);
                *(uint32_t*)(outH + oi + 8 * DH) = h2;
                *(uint32_t*)(outL + oi + 8 * DH) = l2;
            }
        }
    }
}

// ---------------- flash attention (unchanged from R6: 245us, tensor 69%) ---
#define A_SMEM  81920
#define ASTG_B  16384
#define ASTG_S  32768
__global__ __launch_bounds__(128, 2)
void attn_mma(const bf16* __restrict__ Qh, const bf16* __restrict__ Ql,
              const bf16* __restrict__ Kh, const bf16* __restrict__ Kl,
              const bf16* __restrict__ Vh, const bf16* __restrict__ Vl,
              bf16* __restrict__ Ch, bf16* __restrict__ Cl)
{
    extern __shared__ __align__(16) char sm_[];
    const uint32_t sb = smem_to_u32(sm_);
    const int t = threadIdx.x, L = t & 31, wid = t >> 5;
    const int bh = blockIdx.y, q0 = blockIdx.x * 64;
    const int g = L >> 2, tg = L & 3;

    const int a_row = wid * 16 + ((L >> 3) & 1) * 8 + (L & 7);
    const int a_cb  = (L >> 4);
    const int k_row_off = ((L >> 4) & 1) * 8 + (L & 7);
    const int k_cb  = ((L >> 3) & 1);
    const int v_row_off = ((L >> 3) & 1) * 8 + (L & 7);
    const int v_cb  = (L >> 4);
    const int sw    = L & 7;

    auto copy_kv = [&](int st, int kb) {
        const uint32_t base = sb + ASTG_B + st * ASTG_S;
        const size_t goff = ((size_t)bh * SQL + kb * 64) * DH;
        const char* kh = (const char*)(Kh + goff);
        const char* kl = (const char*)(Kl + goff);
        const char* vh = (const char*)(Vh + goff);
        const char* vl = (const char*)(Vl + goff);
#pragma unroll
        for (int i = 0; i < 4; i++) {
            const int u = t + i * 128, r = u >> 3, c = u & 7;
            const uint32_t so = r * 128 + ((c ^ (r & 7)) << 4);
            const int go = r * 128 + c * 16;
            CP16(base + so,         kh + go);
            CP16(base + 8192 + so,  kl + go);
            CP16(base + 16384 + so, vh + go);
            CP16(base + 24576 + so, vl + go);
        }
    };

    copy_kv(0, 0);
    {
        const char* qh = (const char*)(Qh + ((size_t)bh * SQL + q0) * DH);
        const char* ql = (const char*)(Ql + ((size_t)bh * SQL + q0) * DH);
#pragma unroll
        for (int i = 0; i < 4; i++) {
            const int u = t + i * 128, r = u >> 3, c = u & 7;
            const uint32_t so = r * 128 + ((c ^ (r & 7)) << 4);
            const int go = r * 128 + c * 16;
            CP16(sb + so,        qh + go);
            CP16(sb + 8192 + so, ql + go);
        }
    }
    CP_COMMIT();
    CP_WAIT(0);
    __syncthreads();

    uint32_t qH[4][4], qL[4][4];
#pragma unroll
    for (int ks = 0; ks < 4; ks++) {
        const uint32_t qa = sb + a_row * 128 + (((2 * ks + a_cb) ^ sw) << 4);
        ldsm4(qH[ks], qa);
        ldsm4(qL[ks], qa + 8192);
    }

    float oacc[8][4];
#pragma unroll
    for (int a = 0; a < 8; a++)
#pragma unroll
        for (int b = 0; b < 4; b++) oacc[a][b] = 0.0f;
    float m0r = -1e30f, m1r = -1e30f, l0r = 0.0f, l1r = 0.0f;

    for (int kb = 0; kb < 32; kb++) {
        const int cur = kb & 1;
        if (kb < 31) { copy_kv(1 - cur, kb + 1); CP_COMMIT(); CP_WAIT(1); }
        else CP_WAIT(0);
        __syncthreads();
        const uint32_t kbase = sb + ASTG_B + cur * ASTG_S;

        float sacc[8][4];
#pragma unroll
        for (int j = 0; j < 8; j++)
#pragma unroll
            for (int c = 0; c < 4; c++) sacc[j][c] = 0.0f;

#pragma unroll
        for (int ks = 0; ks < 4; ks++) {
#pragma unroll
            for (int jp = 0; jp < 4; jp++) {
                uint32_t kh4[4], kl4[4];
                const int krow = jp * 16 + k_row_off;
                const uint32_t ka = kbase + krow * 128 + (((2 * ks + k_cb) ^ sw) << 4);
                ldsm4(kh4, ka);
                ldsm4(kl4, ka + 8192);
                mma16816(sacc[2 * jp],     qH[ks], &kh4[0]);
                mma16816(sacc[2 * jp],     qH[ks], &kl4[0]);
                mma16816(sacc[2 * jp],     qL[ks], &kh4[0]);
                mma16816(sacc[2 * jp + 1], qH[ks], &kh4[2]);
                mma16816(sacc[2 * jp + 1], qH[ks], &kl4[2]);
                mma16816(sacc[2 * jp + 1], qL[ks], &kh4[2]);
            }
        }

        float rx0 = -1e30f, rx1 = -1e30f;
#pragma unroll
        for (int j = 0; j < 8; j++) {
            rx0 = fmaxf(rx0, fmaxf(sacc[j][0], sacc[j][1]));
            rx1 = fmaxf(rx1, fmaxf(sacc[j][2], sacc[j][3]));
        }
        rx0 = fmaxf(rx0, __shfl_xor_sync(0xffffffffu, rx0, 1));
        rx0 = fmaxf(rx0, __shfl_xor_sync(0xffffffffu, rx0, 2));
        rx1 = fmaxf(rx1, __shfl_xor_sync(0xffffffffu, rx1, 1));
        rx1 = fmaxf(rx1, __shfl_xor_sync(0xffffffffu, rx1, 2));
        const float mn0 = fmaxf(m0r, rx0), mn1 = fmaxf(m1r, rx1);
        const float al0 = ex2(m0r - mn0), al1 = ex2(m1r - mn1);
        m0r = mn0; m1r = mn1;

        float rs0 = 0.0f, rs1 = 0.0f;
#pragma unroll
        for (int j = 0; j < 8; j++) {
            const float p0 = ex2(sacc[j][0] - mn0);
            const float p1 = ex2(sacc[j][1] - mn0);
            const float p2 = ex2(sacc[j][2] - mn1);
            const float p3 = ex2(sacc[j][3] - mn1);
            sacc[j][0] = p0; sacc[j][1] = p1; sacc[j][2] = p2; sacc[j][3] = p3;
            rs0 += p0 + p1; rs1 += p2 + p3;
        }
        rs0 += __shfl_xor_sync(0xffffffffu, rs0, 1);
        rs0 += __shfl_xor_sync(0xffffffffu, rs0, 2);
        rs1 += __shfl_xor_sync(0xffffffffu, rs1, 1);
        rs1 += __shfl_xor_sync(0xffffffffu, rs1, 2);
        l0r = l0r * al0 + rs0;
        l1r = l1r * al1 + rs1;
#pragma unroll
        for (int jd = 0; jd < 8; jd++) {
            oacc[jd][0] *= al0; oacc[jd][1] *= al0;
            oacc[jd][2] *= al1; oacc[jd][3] *= al1;
        }

#pragma unroll
        for (int ks2 = 0; ks2 < 4; ks2++) {
            uint32_t ph[4], pl[4];
            split2(sacc[2 * ks2][0],     sacc[2 * ks2][1],     ph[0], pl[0]);
            split2(sacc[2 * ks2][2],     sacc[2 * ks2][3],     ph[1], pl[1]);
            split2(sacc[2 * ks2 + 1][0], sacc[2 * ks2 + 1][1], ph[2], pl[2]);
            split2(sacc[2 * ks2 + 1][2], sacc[2 * ks2 + 1][3], ph[3], pl[3]);
#pragma unroll
            for (int jdp = 0; jdp < 4; jdp++) {
                uint32_t vh4[4], vl4[4];
                const int vrow = ks2 * 16 + v_row_off;
                const uint32_t va = kbase + 16384 + vrow * 128
                                  + (((2 * jdp + v_cb) ^ sw) << 4);
                ldsm4t(vh4, va);
                ldsm4t(vl4, va + 8192);
                mma16816(oacc[2 * jdp],     ph, &vh4[0]);
                mma16816(oacc[2 * jdp],     ph, &vl4[0]);
                mma16816(oacc[2 * jdp],     pl, &vh4[0]);
                mma16816(oacc[2 * jdp + 1], ph, &vh4[2]);
                mma16816(oacc[2 * jdp + 1], ph, &vl4[2]);
                mma16816(oacc[2 * jdp + 1], pl, &vh4[2]);
            }
        }
        __syncthreads();
    }

    const float inv0 = 1.0f / l0r, inv1 = 1.0f / l1r;
    const int b_ = bh >> 4, h_ = bh & 15;
    const int q_g = q0 + wid * 16 + g;
    const size_t base0 = ((size_t)(b_ * SQL + q_g)) * DM + h_ * DH;
    const size_t base1 = base0 + (size_t)8 * DM;
#pragma unroll
    for (int jd = 0; jd < 8; jd++) {
        const int dcol = jd * 8 + 2 * tg;
        uint32_t h2, l2;
        split2(oacc[jd][0] * inv0, oacc[jd][1] * inv0, h2, l2);
        *(uint32_t*)(Ch + base0 + dcol) = h2;
        *(uint32_t*)(Cl + base0 + dcol) = l2;
        split2(oacc[jd][2] * inv1, oacc[jd][3] * inv1, h2, l2);
        *(uint32_t*)(Ch + base1 + dcol) = h2;
        *(uint32_t*)(Cl + base1 + dcol) = l2;
    }
}

// ---------------------------------------------------------------------------
extern "C" void kernel_launch(void* const* d_in, const int* in_sizes, int n_in,
                              void* d_out, int out_size)
{
    const float* x1 = (const float*)d_in[0];
    const float* x2 = (const float*)d_in[1];
    const float* Wq = (const float*)d_in[2];
    const float* bq = (const float*)d_in[3];
    const float* Wk = (const float*)d_in[4];
    const float* bk = (const float*)d_in[5];
    const float* Wv = (const float*)d_in[6];
    const float* bv = (const float*)d_in[7];
    const float* Wo = (const float*)d_in[8];
    const float* bo = (const float*)d_in[9];
    float* out = (float*)d_out;

    bf16 *Qh, *Ql, *Kh, *Kl, *Vh, *Vl, *Ah, *Al, *Bh, *Bl;
    bf16 *Wqh, *Wql, *Wkh, *Wkl, *Wvh, *Wvl, *Woh, *Wol;
    cudaGetSymbolAddress((void**)&Qh, g_Qh);  cudaGetSymbolAddress((void**)&Ql, g_Ql);
    cudaGetSymbolAddress((void**)&Kh, g_Kh);  cudaGetSymbolAddress((void**)&Kl, g_Kl);
    cudaGetSymbolAddress((void**)&Vh, g_Vh);  cudaGetSymbolAddress((void**)&Vl, g_Vl);
    cudaGetSymbolAddress((void**)&Ah, g_Ah);  cudaGetSymbolAddress((void**)&Al, g_Al);
    cudaGetSymbolAddress((void**)&Bh, g_Bh);  cudaGetSymbolAddress((void**)&Bl, g_Bl);
    cudaGetSymbolAddress((void**)&Wqh, g_Wqh); cudaGetSymbolAddress((void**)&Wql, g_Wql);
    cudaGetSymbolAddress((void**)&Wkh, g_Wkh); cudaGetSymbolAddress((void**)&Wkl, g_Wkl);
    cudaGetSymbolAddress((void**)&Wvh, g_Wvh); cudaGetSymbolAddress((void**)&Wvl, g_Wvl);
    cudaGetSymbolAddress((void**)&Woh, g_Woh); cudaGetSymbolAddress((void**)&Wol, g_Wol);

    cudaFuncSetAttribute(attn_mma,
                         cudaFuncAttributeMaxDynamicSharedMemorySize, A_SMEM);
    cudaFuncSetAttribute(gemm_mma,
                         cudaFuncAttributeMaxDynamicSharedMemorySize, 3 * GSTG);

    const float qscale = 0.125f * 1.4426950408889634f;

    // all splits (x1, x2, Wq, Wk, Wv, Wo) in one launch
    {
        SArgs sa;
        sa.s[0] = x1; sa.h[0] = Ah;  sa.l[0] = Al;
        sa.s[1] = x2; sa.h[1] = Bh;  sa.l[1] = Bl;
        sa.s[2] = Wq; sa.h[2] = Wqh; sa.l[2] = Wql;
        sa.s[3] = Wk; sa.h[3] = Wkh; sa.l[3] = Wkl;
        sa.s[4] = Wv; sa.h[4] = Wvh; sa.l[4] = Wvl;
        sa.s[5] = Wo; sa.h[5] = Woh; sa.l[5] = Wol;
        convS_kernel<<<8192 + 4 * 1024, 256>>>(sa);
    }

    // fused QKV projections
    {
        GArgs ga;
        ga.Ah[0] = Ah; ga.Al[0] = Al; ga.Wh[0] = Wqh; ga.Wl[0] = Wql;
        ga.bias[0] = bq; ga.oh[0] = Qh; ga.ol[0] = Ql; ga.of[0] = 0; ga.scale[0] = qscale;
        ga.Ah[1] = Bh; ga.Al[1] = Bl; ga.Wh[1] = Wkh; ga.Wl[1] = Wkl;
        ga.bias[1] = bk; ga.oh[1] = Kh; ga.ol[1] = Kl; ga.of[1] = 0; ga.scale[1] = 1.0f;
        ga.Ah[2] = Bh; ga.Al[2] = Bl; ga.Wh[2] = Wvh; ga.Wl[2] = Wvl;
        ga.bias[2] = bv; ga.oh[2] = Vh; ga.ol[2] = Vl; ga.of[2] = 0; ga.scale[2] = 1.0f;
        gemm_mma<<<dim3(DM/128, ROWS/64, 3), 128, 3 * GSTG>>>(ga);
    }

    // attention -> ctx split (overwrites Ah/Al)
    attn_mma<<<dim3(SQL/64, BH), 128, A_SMEM>>>(Qh, Ql, Kh, Kl, Vh, Vl, Ah, Al);

    // out = ctx @ Wo + bo (fp32)
    {
        GArgs ga;
        ga.Ah[0] = Ah; ga.Al[0] = Al; ga.Wh[0] = Woh; ga.Wl[0] = Wol;
        ga.bias[0] = bo; ga.oh[0] = 0; ga.ol[0] = 0; ga.of[0] = out; ga.scale[0] = 1.0f;
        gemm_mma<<<dim3(DM/128, ROWS/64, 1), 128, 3 * GSTG>>>(ga);
    }
}